// round 11
// baseline (speedup 1.0000x reference)
#include <cuda_runtime.h>
#include <cuda_fp16.h>
#include <cstdint>
#include <cstddef>

#define DI __device__ __forceinline__
typedef unsigned long long ull;

static constexpr int ZDIM = 512;
static constexpr int MSZ  = 100;
static constexpr int NT   = 13;                      // n8 tiles (104 >= 100)
static constexpr int TSTEPS = ZDIM / 16;             // 32 k16-tiles
static constexpr int EXP_STR   = 106;                // even (LDS.64 aligned), conflict-free residues
static constexpr int SA_FLOATS = 128 * EXP_STR;      // 13568 floats = 54272 B
static constexpr int SMEM_DYN  = 2 * SA_FLOATS * 4;  // 108544 B (sA + sC)
static constexpr int STAGE_U4  = NT * 32;            // 416 uint4 = 6656 B per k16 stage

// basis fragments, fragment-ordered: [t 0..31][nt 0..12][lane 0..31] = (b0h,b1h,b0l,b1l)
__device__ uint4 g_bfrag[TSTEPS * STAGE_U4];         // 212,992 B

DI void fma2(ull& d, ull a, ull b) { asm("fma.rn.f32x2 %0, %1, %2, %0;" : "+l"(d) : "l"(a), "l"(b)); }
DI ull pack2(float v) { ull r; asm("mov.b64 %0, {%1, %1};" : "=l"(r) : "f"(v)); return r; }
DI ull pk(float x, float y) { ull r; asm("mov.b64 %0, {%1, %2};" : "=l"(r) : "f"(x), "f"(y)); return r; }
DI float2 unpk(ull v) { float2 f; asm("mov.b64 {%0, %1}, %2;" : "=f"(f.x), "=f"(f.y) : "l"(v)); return f; }
DI ull lds2(const float* p) { float2 v = *(const float2*)p; return pk(v.x, v.y); }

DI uint32_t smem_u32(const void* p) {
    uint32_t a;
    asm("{ .reg .u64 t; cvta.to.shared.u64 t, %1; cvt.u32.u64 %0, t; }" : "=r"(a) : "l"(p));
    return a;
}
DI void cpasync16(uint32_t saddr, const void* g) {
    asm volatile("cp.async.cg.shared.global [%0], [%1], 16;" :: "r"(saddr), "l"(g));
}
DI void cpcommit() { asm volatile("cp.async.commit_group;" ::: "memory"); }
DI void cpwait2()  { asm volatile("cp.async.wait_group 2;" ::: "memory"); }
DI void cpwait0()  { asm volatile("cp.async.wait_group 0;" ::: "memory"); }

// split fp32 pair into f16x2 hi + f16x2 residual-lo
DI void cvt_split(float x, float y, uint32_t& hi, uint32_t& lo) {
    __half2 h = __floats2half2_rn(x, y);
    __half2 l = __floats2half2_rn(x - __low2float(h), y - __high2float(h));
    hi = *reinterpret_cast<uint32_t*>(&h);
    lo = *reinterpret_cast<uint32_t*>(&l);
}

DI void mma16816(float* d, const uint32_t* a, uint32_t b0, uint32_t b1) {
    asm volatile("mma.sync.aligned.m16n8k16.row.col.f32.f16.f16.f32 "
        "{%0,%1,%2,%3}, {%4,%5,%6,%7}, {%8,%9}, {%0,%1,%2,%3};"
        : "+f"(d[0]), "+f"(d[1]), "+f"(d[2]), "+f"(d[3])
        : "r"(a[0]), "r"(a[1]), "r"(a[2]), "r"(a[3]), "r"(b0), "r"(b1));
}

// ---------- pre-kernel: convert basis -> fragment-ordered split-fp16 global array ----------
extern "C" __global__ void __launch_bounds__(256)
conv_basis(const float* __restrict__ basis)
{
    int s = blockIdx.x * 256 + threadIdx.x;          // 0 .. 13311
    if (s >= TSTEPS * STAGE_U4) return;
    int t  = s / STAGE_U4;
    int r  = s - t * STAGE_U4;
    int nt = r >> 5;
    int ln = r & 31;
    int qq = ln & 3;
    int n  = nt * 8 + (ln >> 2);
    uint4 val = make_uint4(0u, 0u, 0u, 0u);
    if (n < MSZ) {
        int k0 = t * 16 + 2 * qq;
        float v0 = basis[(size_t)k0 * MSZ + n];
        float v1 = basis[(size_t)(k0 + 1) * MSZ + n];
        float v2 = basis[(size_t)(k0 + 8) * MSZ + n];
        float v3 = basis[(size_t)(k0 + 9) * MSZ + n];
        cvt_split(v0, v1, val.x, val.z);
        cvt_split(v2, v3, val.y, val.w);
    }
    g_bfrag[s] = val;
}

// ---------- fused kernel: GEMM (2 m-tiles/warp, NT split across warp pairs) + expm ----------
// 8 warps = 4 row-groups (32 rows each) x 2 nt-halves (nt 0..6 / 7..12). CTA covers 128 rows.
extern "C" __global__ void __launch_bounds__(256, 2)
lie_fused(const float* __restrict__ z, float* __restrict__ out)
{
    extern __shared__ float smem[];
    float* sA = smem;                 // lie_alg / W working set (128 x EXP_STR)
    float* sC = smem + SA_FLOATS;     // GEMM: B ring; expm: A^3 buffer
    const uint32_t ring_base = smem_u32(sC);

    const int tid = threadIdx.x, lane = tid & 31, w = tid >> 5;
    const int rg = w & 3;             // row group: rows rg*32 .. rg*32+31
    const int nh = w >> 2;            // nt half: 0 -> nt 0..6, 1 -> nt 7..12
    const int NTH = nh ? 6 : 7;
    const int ntBase = nh * 7;
    const int g = lane >> 2, q = lane & 3;
    const size_t rowBase = (size_t)blockIdx.x * 128;
    const size_t row0 = rowBase + rg * 32 + g;
    const float* za = z + row0 * ZDIM;            // m0, row g
    const float* zb = za + 8 * ZDIM;              // m0, row g+8
    const float* zc = za + 16 * ZDIM;             // m1, row g
    const float* zd = za + 24 * ZDIM;             // m1, row g+8

    // ================= GEMM phase =================
    float acc0[7][4], acc1[7][4];
#pragma unroll
    for (int j = 0; j < 7; j++)
#pragma unroll
        for (int e = 0; e < 4; e++) { acc0[j][e] = 0.f; acc1[j][e] = 0.f; }

    auto issue_stage = [&](int s) {
        const uint4* gsrc = g_bfrag + (size_t)s * STAGE_U4;
        uint32_t sdst = ring_base + (uint32_t)(s & 3) * (STAGE_U4 * 16);
        cpasync16(sdst + tid * 16, gsrc + tid);
        int i2 = tid + 256;
        if (i2 < STAGE_U4) cpasync16(sdst + i2 * 16, gsrc + i2);
    };

    issue_stage(0); cpcommit();
    issue_stage(1); cpcommit();
    issue_stage(2); cpcommit();

    // prefetch first k16-tile of z fragments (8 x float2)
    float2 pa0, pa1, pb0, pb1, pc0, pc1, pd0, pd1;
    {
        const int kb = 2 * q;
        pa0 = *(const float2*)(za + kb); pa1 = *(const float2*)(za + kb + 8);
        pb0 = *(const float2*)(zb + kb); pb1 = *(const float2*)(zb + kb + 8);
        pc0 = *(const float2*)(zc + kb); pc1 = *(const float2*)(zc + kb + 8);
        pd0 = *(const float2*)(zd + kb); pd1 = *(const float2*)(zd + kb + 8);
    }

    for (int t = 0; t < TSTEPS; t++) {
        cpwait2();          // stage t landed (one commit per iteration)
        __syncthreads();    // visibility of stage t; all reads of slot (t-1)&3 done
        if (t + 3 < TSTEPS) issue_stage(t + 3);
        cpcommit();

        uint32_t Ah0[4], Al0[4], Ah1[4], Al1[4];
        cvt_split(pa0.x, pa0.y, Ah0[0], Al0[0]);
        cvt_split(pb0.x, pb0.y, Ah0[1], Al0[1]);
        cvt_split(pa1.x, pa1.y, Ah0[2], Al0[2]);
        cvt_split(pb1.x, pb1.y, Ah0[3], Al0[3]);
        cvt_split(pc0.x, pc0.y, Ah1[0], Al1[0]);
        cvt_split(pd0.x, pd0.y, Ah1[1], Al1[1]);
        cvt_split(pc1.x, pc1.y, Ah1[2], Al1[2]);
        cvt_split(pd1.x, pd1.y, Ah1[3], Al1[3]);
        if (t + 1 < TSTEPS) {
            const int kb = (t + 1) * 16 + 2 * q;
            pa0 = *(const float2*)(za + kb); pa1 = *(const float2*)(za + kb + 8);
            pb0 = *(const float2*)(zb + kb); pb1 = *(const float2*)(zb + kb + 8);
            pc0 = *(const float2*)(zc + kb); pc1 = *(const float2*)(zc + kb + 8);
            pd0 = *(const float2*)(zd + kb); pd1 = *(const float2*)(zd + kb + 8);
        }

        const uint4* bs = (const uint4*)sC + (size_t)(t & 3) * STAGE_U4 + ntBase * 32 + lane;

        if (nh == 0) {      // 7 n-tiles; one LDS.128 per nt serves both m-tiles (dep distance 14)
            uint4 bb[7];
#pragma unroll
            for (int j = 0; j < 7; j++) bb[j] = bs[j * 32];
#pragma unroll
            for (int j = 0; j < 7; j++) mma16816(acc0[j], Ah0, bb[j].x, bb[j].y);
#pragma unroll
            for (int j = 0; j < 7; j++) mma16816(acc1[j], Ah1, bb[j].x, bb[j].y);
#pragma unroll
            for (int j = 0; j < 7; j++) mma16816(acc0[j], Al0, bb[j].x, bb[j].y);
#pragma unroll
            for (int j = 0; j < 7; j++) mma16816(acc1[j], Al1, bb[j].x, bb[j].y);
#pragma unroll
            for (int j = 0; j < 7; j++) mma16816(acc0[j], Ah0, bb[j].z, bb[j].w);
#pragma unroll
            for (int j = 0; j < 7; j++) mma16816(acc1[j], Ah1, bb[j].z, bb[j].w);
        } else {            // 6 n-tiles
            uint4 bb[6];
#pragma unroll
            for (int j = 0; j < 6; j++) bb[j] = bs[j * 32];
#pragma unroll
            for (int j = 0; j < 6; j++) mma16816(acc0[j], Ah0, bb[j].x, bb[j].y);
#pragma unroll
            for (int j = 0; j < 6; j++) mma16816(acc1[j], Ah1, bb[j].x, bb[j].y);
#pragma unroll
            for (int j = 0; j < 6; j++) mma16816(acc0[j], Al0, bb[j].x, bb[j].y);
#pragma unroll
            for (int j = 0; j < 6; j++) mma16816(acc1[j], Al1, bb[j].x, bb[j].y);
#pragma unroll
            for (int j = 0; j < 6; j++) mma16816(acc0[j], Ah0, bb[j].z, bb[j].w);
#pragma unroll
            for (int j = 0; j < 6; j++) mma16816(acc1[j], Ah1, bb[j].z, bb[j].w);
        }
    }

    // epilogue: fragments -> sA in expm layout (warps write disjoint column ranges)
    {
        const int rl0 = rg * 32 + g;
#pragma unroll
        for (int j = 0; j < 7; j++) {
            if (j < NTH) {
                int col = (ntBase + j) * 8 + 2 * q;
                if (col < MSZ) {
                    *(float2*)(sA + (rl0     ) * EXP_STR + col) = make_float2(acc0[j][0], acc0[j][1]);
                    *(float2*)(sA + (rl0 +  8) * EXP_STR + col) = make_float2(acc0[j][2], acc0[j][3]);
                    *(float2*)(sA + (rl0 + 16) * EXP_STR + col) = make_float2(acc1[j][0], acc1[j][1]);
                    *(float2*)(sA + (rl0 + 24) * EXP_STR + col) = make_float2(acc1[j][2], acc1[j][3]);
                }
            }
        }
    }
    cpwait0();           // drain async groups before sC reuse
    __syncthreads();     // lie_alg complete in sA; ring dead

    // ================= expm: 128 matrices, 2 threads/matrix =================
    // E = I + A + A^2/2 + A^3/6 + A^3*(A/24 + A^2/120 + A^3/720)
    {
        const int m  = tid >> 1;       // local matrix 0..127
        const int h  = tid & 1;
        const int i0 = 5 * h;
        const int mb = m * EXP_STR;

        ull acc2[5][5];
#pragma unroll
        for (int ii = 0; ii < 5; ii++)
#pragma unroll
            for (int jp = 0; jp < 5; jp++) acc2[ii][jp] = 0ull;

        // A^2 (own rows) -> acc2
#pragma unroll
        for (int kp = 0; kp < 5; kp++) {
            const int k0 = 2 * kp, k1 = k0 + 1;
            ull r0[5], r1[5];
#pragma unroll
            for (int jp = 0; jp < 5; jp++) {
                r0[jp] = lds2(sA + mb + k0 * 10 + 2 * jp);
                r1[jp] = lds2(sA + mb + k1 * 10 + 2 * jp);
            }
#pragma unroll
            for (int ii = 0; ii < 5; ii++) {
                float2 za2 = *(const float2*)(sA + mb + (i0 + ii) * 10 + k0);
                ull z0 = pack2(za2.x), z1 = pack2(za2.y);
#pragma unroll
                for (int jp = 0; jp < 5; jp++) { fma2(acc2[ii][jp], z0, r0[jp]); fma2(acc2[ii][jp], z1, r1[jp]); }
            }
        }

        // A^3 = A^2 @ A -> sC (two row-groups to bound register pressure)
#pragma unroll
        for (int grp = 0; grp < 2; grp++) {
            const int gbase = grp * 3;
            const int rows  = grp == 0 ? 3 : 2;
            ull a3[3][5];
#pragma unroll
            for (int ii = 0; ii < 3; ii++)
#pragma unroll
                for (int jp = 0; jp < 5; jp++) a3[ii][jp] = 0ull;
#pragma unroll
            for (int kp = 0; kp < 5; kp++) {
                const int k0 = 2 * kp, k1 = k0 + 1;
                ull r0[5], r1[5];
#pragma unroll
                for (int jp = 0; jp < 5; jp++) {
                    r0[jp] = lds2(sA + mb + k0 * 10 + 2 * jp);
                    r1[jp] = lds2(sA + mb + k1 * 10 + 2 * jp);
                }
#pragma unroll
                for (int ii = 0; ii < 3; ii++) {
                    if (ii < rows) {
                        float2 f = unpk(acc2[gbase + ii][kp]);
                        ull z0 = pack2(f.x), z1 = pack2(f.y);
#pragma unroll
                        for (int jp = 0; jp < 5; jp++) { fma2(a3[ii][jp], z0, r0[jp]); fma2(a3[ii][jp], z1, r1[jp]); }
                    }
                }
            }
#pragma unroll
            for (int ii = 0; ii < 3; ii++) {
                if (ii < rows) {
                    const int gi = i0 + gbase + ii;
#pragma unroll
                    for (int jp = 0; jp < 5; jp++)
                        *(float2*)(sC + mb + gi * 10 + 2 * jp) = unpk(a3[ii][jp]);
                }
            }
        }
        __syncthreads();   // all matmul reads of A complete before W overwrite

        // W = A/24 + A^2/120 + A^3/720 -> sA (own rows); U = I + A + A^2/2 + A^3/6 -> acc2
        {
            const float c2 = 0.5f, c3 = 1.f/6.f, c4 = 1.f/24.f, c5 = 1.f/120.f, c6 = 1.f/720.f;
#pragma unroll
            for (int ii = 0; ii < 5; ii++) {
                const int gi = i0 + ii;
#pragma unroll
                for (int jp = 0; jp < 5; jp++) {
                    float2 a  = *(const float2*)(sA + mb + gi * 10 + 2 * jp);
                    float2 b3 = *(const float2*)(sC + mb + gi * 10 + 2 * jp);
                    float2 b2 = unpk(acc2[ii][jp]);
                    float wx = a.x * c4 + b2.x * c5 + b3.x * c6;
                    float wy = a.y * c4 + b2.y * c5 + b3.y * c6;
                    float ux = (gi == 2 * jp     ? 1.f : 0.f) + a.x + b2.x * c2 + b3.x * c3;
                    float uy = (gi == 2 * jp + 1 ? 1.f : 0.f) + a.y + b2.y * c2 + b3.y * c3;
                    *(float2*)(sA + mb + gi * 10 + 2 * jp) = make_float2(wx, wy);
                    acc2[ii][jp] = pk(ux, uy);
                }
            }
        }
        __syncthreads();   // W complete in sA

        // E = U + A^3 @ W  (A^3 from sC own rows; W rows from sA)
#pragma unroll
        for (int kp = 0; kp < 5; kp++) {
            const int k0 = 2 * kp, k1 = k0 + 1;
            ull r0[5], r1[5];
#pragma unroll
            for (int jp = 0; jp < 5; jp++) {
                r0[jp] = lds2(sA + mb + k0 * 10 + 2 * jp);
                r1[jp] = lds2(sA + mb + k1 * 10 + 2 * jp);
            }
#pragma unroll
            for (int ii = 0; ii < 5; ii++) {
                float2 f = *(const float2*)(sC + mb + (i0 + ii) * 10 + k0);
                ull z0 = pack2(f.x), z1 = pack2(f.y);
#pragma unroll
                for (int jp = 0; jp < 5; jp++) { fma2(acc2[ii][jp], z0, r0[jp]); fma2(acc2[ii][jp], z1, r1[jp]); }
            }
        }

        // store own 5 rows (50 contiguous floats)
        float* op = out + (rowBase + m) * MSZ + i0 * 10;
#pragma unroll
        for (int ii = 0; ii < 5; ii++)
#pragma unroll
            for (int jp = 0; jp < 5; jp++)
                *(float2*)(op + ii * 10 + 2 * jp) = unpk(acc2[ii][jp]);
    }
}

// ---------------- launch ----------------
extern "C" void kernel_launch(void* const* d_in, const int* in_sizes, int n_in,
                              void* d_out, int out_size)
{
    const float* z     = (const float*)d_in[0];   // [B, 512]
    const float* basis = (const float*)d_in[1];   // [512, 10, 10]
    float* out = (float*)d_out;                   // [B, 10, 10]

    int B = in_sizes[0] / ZDIM;                   // 131072

    cudaFuncSetAttribute(lie_fused, cudaFuncAttributeMaxDynamicSharedMemorySize, SMEM_DYN);

    conv_basis<<<52, 256>>>(basis);               // 13312 fragment slots
    lie_fused<<<B / 128, 256, SMEM_DYN>>>(z, out);
}

// round 12
// speedup vs baseline: 1.2397x; 1.2397x over previous
#include <cuda_runtime.h>
#include <cuda_fp16.h>
#include <cstdint>
#include <cstddef>

#define DI __device__ __forceinline__
typedef unsigned long long ull;

static constexpr int ZDIM = 512;
static constexpr int MSZ  = 100;
static constexpr int NT   = 13;                      // n8 tiles (104 >= 100)
static constexpr int TSTEPS = ZDIM / 16;             // 32 k16-tiles
static constexpr int EXP_STR   = 106;                // even (LDS.64 aligned), conflict-free residues
static constexpr int SA_FLOATS = 128 * EXP_STR;      // 13568 floats = 54272 B
static constexpr int SMEM_DYN  = 2 * SA_FLOATS * 4;  // 108544 B (sA + sC)
static constexpr int STAGE_U2  = NT * 32;            // 416 uint2 = 3328 B per k16 stage

// basis fragments (hi only), fragment-ordered: [t][nt][lane] = (b0h, b1h)
__device__ uint2 g_bfrag[TSTEPS * STAGE_U2];         // 106,496 B (L2-resident)

DI void fma2(ull& d, ull a, ull b) { asm("fma.rn.f32x2 %0, %1, %2, %0;" : "+l"(d) : "l"(a), "l"(b)); }
DI ull pack2(float v) { ull r; asm("mov.b64 %0, {%1, %1};" : "=l"(r) : "f"(v)); return r; }
DI ull pk(float x, float y) { ull r; asm("mov.b64 %0, {%1, %2};" : "=l"(r) : "f"(x), "f"(y)); return r; }
DI float2 unpk(ull v) { float2 f; asm("mov.b64 {%0, %1}, %2;" : "=f"(f.x), "=f"(f.y) : "l"(v)); return f; }
DI ull lds2(const float* p) { float2 v = *(const float2*)p; return pk(v.x, v.y); }

DI uint32_t smem_u32(const void* p) {
    uint32_t a;
    asm("{ .reg .u64 t; cvta.to.shared.u64 t, %1; cvt.u32.u64 %0, t; }" : "=r"(a) : "l"(p));
    return a;
}
DI void cpasync16(uint32_t saddr, const void* g) {
    asm volatile("cp.async.cg.shared.global [%0], [%1], 16;" :: "r"(saddr), "l"(g));
}
DI void cpcommit() { asm volatile("cp.async.commit_group;" ::: "memory"); }
DI void cpwait2()  { asm volatile("cp.async.wait_group 2;" ::: "memory"); }
DI void cpwait0()  { asm volatile("cp.async.wait_group 0;" ::: "memory"); }

// split fp32 pair into f16x2 hi + f16x2 residual-lo (for A = z)
DI void cvt_split(float x, float y, uint32_t& hi, uint32_t& lo) {
    __half2 h = __floats2half2_rn(x, y);
    __half2 l = __floats2half2_rn(x - __low2float(h), y - __high2float(h));
    hi = *reinterpret_cast<uint32_t*>(&h);
    lo = *reinterpret_cast<uint32_t*>(&l);
}
DI uint32_t cvt_hi(float x, float y) {
    __half2 h = __floats2half2_rn(x, y);
    return *reinterpret_cast<uint32_t*>(&h);
}

DI void mma16816(float* d, const uint32_t* a, uint32_t b0, uint32_t b1) {
    asm volatile("mma.sync.aligned.m16n8k16.row.col.f32.f16.f16.f32 "
        "{%0,%1,%2,%3}, {%4,%5,%6,%7}, {%8,%9}, {%0,%1,%2,%3};"
        : "+f"(d[0]), "+f"(d[1]), "+f"(d[2]), "+f"(d[3])
        : "r"(a[0]), "r"(a[1]), "r"(a[2]), "r"(a[3]), "r"(b0), "r"(b1));
}

// ---------- pre-kernel: convert basis -> fragment-ordered fp16 global array (hi only) ----------
extern "C" __global__ void __launch_bounds__(256)
conv_basis(const float* __restrict__ basis)
{
    int s = blockIdx.x * 256 + threadIdx.x;          // 0 .. 13311
    if (s >= TSTEPS * STAGE_U2) return;
    int t  = s / STAGE_U2;
    int r  = s - t * STAGE_U2;
    int nt = r >> 5;
    int ln = r & 31;
    int qq = ln & 3;
    int n  = nt * 8 + (ln >> 2);
    uint2 val = make_uint2(0u, 0u);
    if (n < MSZ) {
        int k0 = t * 16 + 2 * qq;
        val.x = cvt_hi(basis[(size_t)k0 * MSZ + n],       basis[(size_t)(k0 + 1) * MSZ + n]);
        val.y = cvt_hi(basis[(size_t)(k0 + 8) * MSZ + n], basis[(size_t)(k0 + 9) * MSZ + n]);
    }
    g_bfrag[s] = val;
}

// ---------- fused kernel: GEMM (split-A x fp16-B, 2-pass mma.sync) + expm ----------
extern "C" __global__ void __launch_bounds__(256, 2)
lie_fused(const float* __restrict__ z, float* __restrict__ out)
{
    extern __shared__ float smem[];
    float* sA = smem;                 // lie_alg / W working set
    float* sC = smem + SA_FLOATS;     // GEMM: B ring; expm: A^3 buffer
    const uint32_t ring_base = smem_u32(sC);

    const int tid = threadIdx.x, lane = tid & 31, w = tid >> 5;
    const int g = lane >> 2, q = lane & 3;
    const size_t rowBase = (size_t)blockIdx.x * 128;
    const size_t row0 = rowBase + w * 16 + g;
    const float* zr0 = z + row0 * ZDIM;
    const float* zr1 = zr0 + 8 * ZDIM;

    // ================= GEMM phase =================
    float acc[NT][4];
#pragma unroll
    for (int nt = 0; nt < NT; nt++) { acc[nt][0]=0.f; acc[nt][1]=0.f; acc[nt][2]=0.f; acc[nt][3]=0.f; }

    // cp.async stage issuer: stage s -> ring slot s&3 (3328 B = 208 x 16B)
    auto issue_stage = [&](int s) {
        const char* gsrc = (const char*)(g_bfrag + (size_t)s * STAGE_U2);
        uint32_t sdst = ring_base + (uint32_t)(s & 3) * (STAGE_U2 * 8);
        if (tid < 208) cpasync16(sdst + tid * 16, gsrc + tid * 16);
    };

    issue_stage(0); cpcommit();
    issue_stage(1); cpcommit();
    issue_stage(2); cpcommit();

    // prefetch first k16-tile of z fragments
    float2 p00, p01, p10, p11;
    {
        const int kb = 2 * q;
        p00 = *(const float2*)(zr0 + kb);  p01 = *(const float2*)(zr0 + kb + 8);
        p10 = *(const float2*)(zr1 + kb);  p11 = *(const float2*)(zr1 + kb + 8);
    }

    for (int t = 0; t < TSTEPS; t++) {
        cpwait2();          // stage t landed (one commit per iteration)
        __syncthreads();    // visibility of stage t; all reads of slot (t-1)&3 done
        if (t + 3 < TSTEPS) issue_stage(t + 3);
        cpcommit();

        uint32_t Ah[4], Al[4];
        cvt_split(p00.x, p00.y, Ah[0], Al[0]);   // (row g,   k lo)
        cvt_split(p10.x, p10.y, Ah[1], Al[1]);   // (row g+8, k lo)
        cvt_split(p01.x, p01.y, Ah[2], Al[2]);   // (row g,   k hi)
        cvt_split(p11.x, p11.y, Ah[3], Al[3]);   // (row g+8, k hi)
        if (t + 1 < TSTEPS) {
            const int kb = (t + 1) * 16 + 2 * q;
            p00 = *(const float2*)(zr0 + kb);  p01 = *(const float2*)(zr0 + kb + 8);
            p10 = *(const float2*)(zr1 + kb);  p11 = *(const float2*)(zr1 + kb + 8);
        }

        const uint2* bs = (const uint2*)sC + (size_t)(t & 3) * STAGE_U2 + lane;

        // 13 n-tiles, LDS.64 conflict-free; 2 passes, dep distance 13
        uint2 bb[NT];
#pragma unroll
        for (int j = 0; j < NT; j++) bb[j] = bs[j * 32];
#pragma unroll
        for (int j = 0; j < NT; j++) mma16816(acc[j], Ah, bb[j].x, bb[j].y);   // hi*B
#pragma unroll
        for (int j = 0; j < NT; j++) mma16816(acc[j], Al, bb[j].x, bb[j].y);   // lo*B
    }

    // epilogue: fragments -> sA in expm layout
    {
        const int rl0 = w * 16 + g;
#pragma unroll
        for (int nt = 0; nt < NT; nt++) {
            int col = nt * 8 + 2 * q;
            if (col < MSZ) {
                *(float2*)(sA + rl0 * EXP_STR + col)       = make_float2(acc[nt][0], acc[nt][1]);
                *(float2*)(sA + (rl0 + 8) * EXP_STR + col) = make_float2(acc[nt][2], acc[nt][3]);
            }
        }
    }
    cpwait0();           // drain async groups before sC reuse
    __syncthreads();     // lie_alg complete in sA; ring dead

    // ================= expm: E = I + A + A^2/2 + A^3/6 + A^3*(A/24 + A^2/120 + A^3/720) =====
    {
        const int m  = tid >> 1;       // local matrix 0..127
        const int h  = tid & 1;
        const int i0 = 5 * h;
        const int mb = m * EXP_STR;

        ull acc2[5][5];
#pragma unroll
        for (int ii = 0; ii < 5; ii++)
#pragma unroll
            for (int jp = 0; jp < 5; jp++) acc2[ii][jp] = 0ull;

        // A^2 (own rows) -> acc2
#pragma unroll
        for (int kp = 0; kp < 5; kp++) {
            const int k0 = 2 * kp, k1 = k0 + 1;
            ull r0[5], r1[5];
#pragma unroll
            for (int jp = 0; jp < 5; jp++) {
                r0[jp] = lds2(sA + mb + k0 * 10 + 2 * jp);
                r1[jp] = lds2(sA + mb + k1 * 10 + 2 * jp);
            }
#pragma unroll
            for (int ii = 0; ii < 5; ii++) {
                float2 za2 = *(const float2*)(sA + mb + (i0 + ii) * 10 + k0);
                ull z0 = pack2(za2.x), z1 = pack2(za2.y);
#pragma unroll
                for (int jp = 0; jp < 5; jp++) { fma2(acc2[ii][jp], z0, r0[jp]); fma2(acc2[ii][jp], z1, r1[jp]); }
            }
        }

        // A^3 = A^2 @ A -> sC (two row-groups to bound register pressure)
#pragma unroll
        for (int grp = 0; grp < 2; grp++) {
            const int gbase = grp * 3;
            const int rows  = grp == 0 ? 3 : 2;
            ull a3[3][5];
#pragma unroll
            for (int ii = 0; ii < 3; ii++)
#pragma unroll
                for (int jp = 0; jp < 5; jp++) a3[ii][jp] = 0ull;
#pragma unroll
            for (int kp = 0; kp < 5; kp++) {
                const int k0 = 2 * kp, k1 = k0 + 1;
                ull r0[5], r1[5];
#pragma unroll
                for (int jp = 0; jp < 5; jp++) {
                    r0[jp] = lds2(sA + mb + k0 * 10 + 2 * jp);
                    r1[jp] = lds2(sA + mb + k1 * 10 + 2 * jp);
                }
#pragma unroll
                for (int ii = 0; ii < 3; ii++) {
                    if (ii < rows) {
                        float2 f = unpk(acc2[gbase + ii][kp]);
                        ull z0 = pack2(f.x), z1 = pack2(f.y);
#pragma unroll
                        for (int jp = 0; jp < 5; jp++) { fma2(a3[ii][jp], z0, r0[jp]); fma2(a3[ii][jp], z1, r1[jp]); }
                    }
                }
            }
#pragma unroll
            for (int ii = 0; ii < 3; ii++) {
                if (ii < rows) {
                    const int gi = i0 + gbase + ii;
#pragma unroll
                    for (int jp = 0; jp < 5; jp++)
                        *(float2*)(sC + mb + gi * 10 + 2 * jp) = unpk(a3[ii][jp]);
                }
            }
        }
        __syncthreads();   // all matmul reads of A complete before W overwrite

        // W = A/24 + A^2/120 + A^3/720 -> sA (own rows); U = I + A + A^2/2 + A^3/6 -> acc2
        {
            const float c2 = 0.5f, c3 = 1.f/6.f, c4 = 1.f/24.f, c5 = 1.f/120.f, c6 = 1.f/720.f;
#pragma unroll
            for (int ii = 0; ii < 5; ii++) {
                const int gi = i0 + ii;
#pragma unroll
                for (int jp = 0; jp < 5; jp++) {
                    float2 a  = *(const float2*)(sA + mb + gi * 10 + 2 * jp);
                    float2 b3 = *(const float2*)(sC + mb + gi * 10 + 2 * jp);
                    float2 b2 = unpk(acc2[ii][jp]);
                    float wx = a.x * c4 + b2.x * c5 + b3.x * c6;
                    float wy = a.y * c4 + b2.y * c5 + b3.y * c6;
                    float ux = (gi == 2 * jp     ? 1.f : 0.f) + a.x + b2.x * c2 + b3.x * c3;
                    float uy = (gi == 2 * jp + 1 ? 1.f : 0.f) + a.y + b2.y * c2 + b3.y * c3;
                    *(float2*)(sA + mb + gi * 10 + 2 * jp) = make_float2(wx, wy);
                    acc2[ii][jp] = pk(ux, uy);
                }
            }
        }
        __syncthreads();   // W complete in sA

        // E = U + A^3 @ W  (A^3 from sC own rows; W rows from sA)
#pragma unroll
        for (int kp = 0; kp < 5; kp++) {
            const int k0 = 2 * kp, k1 = k0 + 1;
            ull r0[5], r1[5];
#pragma unroll
            for (int jp = 0; jp < 5; jp++) {
                r0[jp] = lds2(sA + mb + k0 * 10 + 2 * jp);
                r1[jp] = lds2(sA + mb + k1 * 10 + 2 * jp);
            }
#pragma unroll
            for (int ii = 0; ii < 5; ii++) {
                float2 f = *(const float2*)(sC + mb + (i0 + ii) * 10 + k0);
                ull z0 = pack2(f.x), z1 = pack2(f.y);
#pragma unroll
                for (int jp = 0; jp < 5; jp++) { fma2(acc2[ii][jp], z0, r0[jp]); fma2(acc2[ii][jp], z1, r1[jp]); }
            }
        }

        // store own 5 rows (50 contiguous floats)
        float* op = out + (rowBase + m) * MSZ + i0 * 10;
#pragma unroll
        for (int ii = 0; ii < 5; ii++)
#pragma unroll
            for (int jp = 0; jp < 5; jp++)
                *(float2*)(op + ii * 10 + 2 * jp) = unpk(acc2[ii][jp]);
    }
}

// ---------------- launch ----------------
extern "C" void kernel_launch(void* const* d_in, const int* in_sizes, int n_in,
                              void* d_out, int out_size)
{
    const float* z     = (const float*)d_in[0];   // [B, 512]
    const float* basis = (const float*)d_in[1];   // [512, 10, 10]
    float* out = (float*)d_out;                   // [B, 10, 10]

    int B = in_sizes[0] / ZDIM;                   // 131072

    cudaFuncSetAttribute(lie_fused, cudaFuncAttributeMaxDynamicSharedMemorySize, SMEM_DYN);

    conv_basis<<<52, 256>>>(basis);               // 13312 fragment slots
    lie_fused<<<B / 128, 256, SMEM_DYN>>>(z, out);
}

// round 13
// speedup vs baseline: 1.3741x; 1.1084x over previous
#include <cuda_runtime.h>
#include <cuda_fp16.h>
#include <cstdint>
#include <cstddef>

#define DI __device__ __forceinline__
typedef unsigned long long ull;

static constexpr int ZDIM = 512;
static constexpr int MSZ  = 100;
static constexpr int NT   = 13;                      // n8 tiles (104 >= 100)
static constexpr int TSTEPS = ZDIM / 16;             // 32 k16-tiles
static constexpr int EXP_STR   = 106;                // even (LDS.64 aligned), conflict-free residues
static constexpr int SA_FLOATS = 128 * EXP_STR;      // 13568 floats = 54272 B
static constexpr int SMEM_DYN  = 2 * SA_FLOATS * 4;  // 108544 B (>= whole B: 106496 B)
static constexpr int STAGE_U2  = NT * 32;            // 416 uint2 per k16 stage
static constexpr int B_U2      = TSTEPS * STAGE_U2;  // 13312 uint2 = 106496 B
static constexpr int B_LINES   = B_U2 / 2;           // 6656 x 16B cp.async lines

// basis fragments (fp16 hi only), fragment-ordered: [t][nt][lane] = (b0h, b1h)
__device__ uint2 g_bfrag[B_U2];                      // 106,496 B (L2-resident)

DI void fma2(ull& d, ull a, ull b) { asm("fma.rn.f32x2 %0, %1, %2, %0;" : "+l"(d) : "l"(a), "l"(b)); }
DI ull pack2(float v) { ull r; asm("mov.b64 %0, {%1, %1};" : "=l"(r) : "f"(v)); return r; }
DI ull pk(float x, float y) { ull r; asm("mov.b64 %0, {%1, %2};" : "=l"(r) : "f"(x), "f"(y)); return r; }
DI float2 unpk(ull v) { float2 f; asm("mov.b64 {%0, %1}, %2;" : "=f"(f.x), "=f"(f.y) : "l"(v)); return f; }
DI ull lds2(const float* p) { float2 v = *(const float2*)p; return pk(v.x, v.y); }

DI uint32_t smem_u32(const void* p) {
    uint32_t a;
    asm("{ .reg .u64 t; cvta.to.shared.u64 t, %1; cvt.u32.u64 %0, t; }" : "=r"(a) : "l"(p));
    return a;
}
DI void cpasync16(uint32_t saddr, const void* g) {
    asm volatile("cp.async.cg.shared.global [%0], [%1], 16;" :: "r"(saddr), "l"(g));
}
DI void cpcommit() { asm volatile("cp.async.commit_group;" ::: "memory"); }
DI void cpwait0()  { asm volatile("cp.async.wait_group 0;" ::: "memory"); }

// split fp32 pair into f16x2 hi + f16x2 residual-lo (for A = z)
DI void cvt_split(float x, float y, uint32_t& hi, uint32_t& lo) {
    __half2 h = __floats2half2_rn(x, y);
    __half2 l = __floats2half2_rn(x - __low2float(h), y - __high2float(h));
    hi = *reinterpret_cast<uint32_t*>(&h);
    lo = *reinterpret_cast<uint32_t*>(&l);
}
DI uint32_t cvt_hi(float x, float y) {
    __half2 h = __floats2half2_rn(x, y);
    return *reinterpret_cast<uint32_t*>(&h);
}

DI void mma16816(float* d, const uint32_t* a, uint32_t b0, uint32_t b1) {
    asm volatile("mma.sync.aligned.m16n8k16.row.col.f32.f16.f16.f32 "
        "{%0,%1,%2,%3}, {%4,%5,%6,%7}, {%8,%9}, {%0,%1,%2,%3};"
        : "+f"(d[0]), "+f"(d[1]), "+f"(d[2]), "+f"(d[3])
        : "r"(a[0]), "r"(a[1]), "r"(a[2]), "r"(a[3]), "r"(b0), "r"(b1));
}

// ---------- pre-kernel: convert basis -> fragment-ordered fp16 global array ----------
extern "C" __global__ void __launch_bounds__(256)
conv_basis(const float* __restrict__ basis)
{
    int s = blockIdx.x * 256 + threadIdx.x;          // 0 .. 13311
    if (s >= B_U2) return;
    int t  = s / STAGE_U2;
    int r  = s - t * STAGE_U2;
    int nt = r >> 5;
    int ln = r & 31;
    int qq = ln & 3;
    int n  = nt * 8 + (ln >> 2);
    uint2 val = make_uint2(0u, 0u);
    if (n < MSZ) {
        int k0 = t * 16 + 2 * qq;
        val.x = cvt_hi(basis[(size_t)k0 * MSZ + n],       basis[(size_t)(k0 + 1) * MSZ + n]);
        val.y = cvt_hi(basis[(size_t)(k0 + 8) * MSZ + n], basis[(size_t)(k0 + 9) * MSZ + n]);
    }
    g_bfrag[s] = val;
}

// ---------- fused kernel: GEMM (split-A x fp16-B, 2-pass mma.sync, B fully SMEM-resident) + expm ----------
extern "C" __global__ void __launch_bounds__(256, 2)
lie_fused(const float* __restrict__ z, float* __restrict__ out)
{
    extern __shared__ float smem[];
    float* sA = smem;                 // (after GEMM) lie_alg / W working set
    float* sC = smem + SA_FLOATS;     // (after GEMM) A^3 buffer
    const uint2* sB = (const uint2*)smem;   // (during GEMM) whole B: 13312 uint2
    const uint32_t sb_base = smem_u32(smem);

    const int tid = threadIdx.x, lane = tid & 31, w = tid >> 5;
    const int g = lane >> 2, q = lane & 3;
    const size_t rowBase = (size_t)blockIdx.x * 128;
    const size_t row0 = rowBase + w * 16 + g;
    const float* zr0 = z + row0 * ZDIM;
    const float* zr1 = zr0 + 8 * ZDIM;

    // ---- load ENTIRE B into SMEM once (6656 x 16B lines, 26 per thread) ----
    {
        const char* gsrc = (const char*)g_bfrag;
#pragma unroll
        for (int i = 0; i < B_LINES / 256; i++) {       // 26
            int idx = i * 256 + tid;
            cpasync16(sb_base + idx * 16, gsrc + idx * 16);
        }
        cpcommit();
    }

    // prefetch first k16-tile of z fragments (overlaps with B load)
    float2 p00, p01, p10, p11;
    {
        const int kb = 2 * q;
        p00 = *(const float2*)(zr0 + kb);  p01 = *(const float2*)(zr0 + kb + 8);
        p10 = *(const float2*)(zr1 + kb);  p11 = *(const float2*)(zr1 + kb + 8);
    }

    float acc[NT][4];
#pragma unroll
    for (int nt = 0; nt < NT; nt++) { acc[nt][0]=0.f; acc[nt][1]=0.f; acc[nt][2]=0.f; acc[nt][3]=0.f; }

    cpwait0();
    __syncthreads();     // whole B visible; NO barriers inside the main loop

    // ================= GEMM main loop: barrier-free =================
    for (int t = 0; t < TSTEPS; t++) {
        uint32_t Ah[4], Al[4];
        cvt_split(p00.x, p00.y, Ah[0], Al[0]);   // (row g,   k lo)
        cvt_split(p10.x, p10.y, Ah[1], Al[1]);   // (row g+8, k lo)
        cvt_split(p01.x, p01.y, Ah[2], Al[2]);   // (row g,   k hi)
        cvt_split(p11.x, p11.y, Ah[3], Al[3]);   // (row g+8, k hi)
        if (t + 1 < TSTEPS) {
            const int kb = (t + 1) * 16 + 2 * q;
            p00 = *(const float2*)(zr0 + kb);  p01 = *(const float2*)(zr0 + kb + 8);
            p10 = *(const float2*)(zr1 + kb);  p11 = *(const float2*)(zr1 + kb + 8);
        }

        const uint2* bs = sB + (size_t)t * STAGE_U2 + lane;

        uint2 bb[NT];
#pragma unroll
        for (int j = 0; j < NT; j++) bb[j] = bs[j * 32];   // LDS.64 conflict-free
#pragma unroll
        for (int j = 0; j < NT; j++) mma16816(acc[j], Ah, bb[j].x, bb[j].y);   // hi*B
#pragma unroll
        for (int j = 0; j < NT; j++) mma16816(acc[j], Al, bb[j].x, bb[j].y);   // lo*B
    }

    __syncthreads();     // all warps done reading B before overwriting region as sA/sC

    // epilogue: fragments -> sA in expm layout
    {
        const int rl0 = w * 16 + g;
#pragma unroll
        for (int nt = 0; nt < NT; nt++) {
            int col = nt * 8 + 2 * q;
            if (col < MSZ) {
                *(float2*)(sA + rl0 * EXP_STR + col)       = make_float2(acc[nt][0], acc[nt][1]);
                *(float2*)(sA + (rl0 + 8) * EXP_STR + col) = make_float2(acc[nt][2], acc[nt][3]);
            }
        }
    }
    __syncthreads();     // lie_alg complete in sA

    // ================= expm: E = I + A + A^2/2 + A^3/6 + A^3*(A/24 + A^2/120 + A^3/720) =====
    {
        const int m  = tid >> 1;       // local matrix 0..127
        const int h  = tid & 1;
        const int i0 = 5 * h;
        const int mb = m * EXP_STR;

        ull acc2[5][5];
#pragma unroll
        for (int ii = 0; ii < 5; ii++)
#pragma unroll
            for (int jp = 0; jp < 5; jp++) acc2[ii][jp] = 0ull;

        // A^2 (own rows) -> acc2
#pragma unroll
        for (int kp = 0; kp < 5; kp++) {
            const int k0 = 2 * kp, k1 = k0 + 1;
            ull r0[5], r1[5];
#pragma unroll
            for (int jp = 0; jp < 5; jp++) {
                r0[jp] = lds2(sA + mb + k0 * 10 + 2 * jp);
                r1[jp] = lds2(sA + mb + k1 * 10 + 2 * jp);
            }
#pragma unroll
            for (int ii = 0; ii < 5; ii++) {
                float2 za2 = *(const float2*)(sA + mb + (i0 + ii) * 10 + k0);
                ull z0 = pack2(za2.x), z1 = pack2(za2.y);
#pragma unroll
                for (int jp = 0; jp < 5; jp++) { fma2(acc2[ii][jp], z0, r0[jp]); fma2(acc2[ii][jp], z1, r1[jp]); }
            }
        }

        // A^3 = A^2 @ A -> sC (two row-groups to bound register pressure)
#pragma unroll
        for (int grp = 0; grp < 2; grp++) {
            const int gbase = grp * 3;
            const int rows  = grp == 0 ? 3 : 2;
            ull a3[3][5];
#pragma unroll
            for (int ii = 0; ii < 3; ii++)
#pragma unroll
                for (int jp = 0; jp < 5; jp++) a3[ii][jp] = 0ull;
#pragma unroll
            for (int kp = 0; kp < 5; kp++) {
                const int k0 = 2 * kp, k1 = k0 + 1;
                ull r0[5], r1[5];
#pragma unroll
                for (int jp = 0; jp < 5; jp++) {
                    r0[jp] = lds2(sA + mb + k0 * 10 + 2 * jp);
                    r1[jp] = lds2(sA + mb + k1 * 10 + 2 * jp);
                }
#pragma unroll
                for (int ii = 0; ii < 3; ii++) {
                    if (ii < rows) {
                        float2 f = unpk(acc2[gbase + ii][kp]);
                        ull z0 = pack2(f.x), z1 = pack2(f.y);
#pragma unroll
                        for (int jp = 0; jp < 5; jp++) { fma2(a3[ii][jp], z0, r0[jp]); fma2(a3[ii][jp], z1, r1[jp]); }
                    }
                }
            }
#pragma unroll
            for (int ii = 0; ii < 3; ii++) {
                if (ii < rows) {
                    const int gi = i0 + gbase + ii;
#pragma unroll
                    for (int jp = 0; jp < 5; jp++)
                        *(float2*)(sC + mb + gi * 10 + 2 * jp) = unpk(a3[ii][jp]);
                }
            }
        }
        __syncthreads();   // all matmul reads of A complete before W overwrite

        // W = A/24 + A^2/120 + A^3/720 -> sA (own rows); U = I + A + A^2/2 + A^3/6 -> acc2
        {
            const float c2 = 0.5f, c3 = 1.f/6.f, c4 = 1.f/24.f, c5 = 1.f/120.f, c6 = 1.f/720.f;
#pragma unroll
            for (int ii = 0; ii < 5; ii++) {
                const int gi = i0 + ii;
#pragma unroll
                for (int jp = 0; jp < 5; jp++) {
                    float2 a  = *(const float2*)(sA + mb + gi * 10 + 2 * jp);
                    float2 b3 = *(const float2*)(sC + mb + gi * 10 + 2 * jp);
                    float2 b2 = unpk(acc2[ii][jp]);
                    float wx = a.x * c4 + b2.x * c5 + b3.x * c6;
                    float wy = a.y * c4 + b2.y * c5 + b3.y * c6;
                    float ux = (gi == 2 * jp     ? 1.f : 0.f) + a.x + b2.x * c2 + b3.x * c3;
                    float uy = (gi == 2 * jp + 1 ? 1.f : 0.f) + a.y + b2.y * c2 + b3.y * c3;
                    *(float2*)(sA + mb + gi * 10 + 2 * jp) = make_float2(wx, wy);
                    acc2[ii][jp] = pk(ux, uy);
                }
            }
        }
        __syncthreads();   // W complete in sA

        // E = U + A^3 @ W  (A^3 from sC own rows; W rows from sA)
#pragma unroll
        for (int kp = 0; kp < 5; kp++) {
            const int k0 = 2 * kp, k1 = k0 + 1;
            ull r0[5], r1[5];
#pragma unroll
            for (int jp = 0; jp < 5; jp++) {
                r0[jp] = lds2(sA + mb + k0 * 10 + 2 * jp);
                r1[jp] = lds2(sA + mb + k1 * 10 + 2 * jp);
            }
#pragma unroll
            for (int ii = 0; ii < 5; ii++) {
                float2 f = *(const float2*)(sC + mb + (i0 + ii) * 10 + k0);
                ull z0 = pack2(f.x), z1 = pack2(f.y);
#pragma unroll
                for (int jp = 0; jp < 5; jp++) { fma2(acc2[ii][jp], z0, r0[jp]); fma2(acc2[ii][jp], z1, r1[jp]); }
            }
        }

        // store own 5 rows (50 contiguous floats)
        float* op = out + (rowBase + m) * MSZ + i0 * 10;
#pragma unroll
        for (int ii = 0; ii < 5; ii++)
#pragma unroll
            for (int jp = 0; jp < 5; jp++)
                *(float2*)(op + ii * 10 + 2 * jp) = unpk(acc2[ii][jp]);
    }
}

// ---------------- launch ----------------
extern "C" void kernel_launch(void* const* d_in, const int* in_sizes, int n_in,
                              void* d_out, int out_size)
{
    const float* z     = (const float*)d_in[0];   // [B, 512]
    const float* basis = (const float*)d_in[1];   // [512, 10, 10]
    float* out = (float*)d_out;                   // [B, 10, 10]

    int B = in_sizes[0] / ZDIM;                   // 131072

    cudaFuncSetAttribute(lie_fused, cudaFuncAttributeMaxDynamicSharedMemorySize, SMEM_DYN);

    conv_basis<<<52, 256>>>(basis);               // 13312 fragment slots
    lie_fused<<<B / 128, 256, SMEM_DYN>>>(z, out);
}

// round 14
// speedup vs baseline: 1.4510x; 1.0559x over previous
#include <cuda_runtime.h>
#include <cuda_fp16.h>
#include <cstdint>
#include <cstddef>

#define DI __device__ __forceinline__
typedef unsigned long long ull;

static constexpr int ZDIM = 512;
static constexpr int MSZ  = 100;
static constexpr int NT   = 13;                      // n8 tiles (104 >= 100)
static constexpr int TSTEPS = ZDIM / 16;             // 32 k16-tiles
static constexpr int EXP_STR   = 106;                // even (LDS.64 aligned), conflict-free residues
static constexpr int SA_FLOATS = 128 * EXP_STR;      // 13568 floats = 54272 B
static constexpr int SMEM_DYN  = 2 * SA_FLOATS * 4;  // 108544 B (>= whole B: 106496 B)
static constexpr int STAGE_U2  = NT * 32;            // 416 uint2 per k16 stage
static constexpr int B_U2      = TSTEPS * STAGE_U2;  // 13312 uint2 = 106496 B
static constexpr int B_LINES   = B_U2 / 2;           // 6656 x 16B cp.async lines

// basis fragments (fp16), fragment-ordered: [t][nt][lane] = (b0h, b1h)
__device__ uint2 g_bfrag[B_U2];                      // 106,496 B (L2-resident)

DI void fma2(ull& d, ull a, ull b) { asm("fma.rn.f32x2 %0, %1, %2, %0;" : "+l"(d) : "l"(a), "l"(b)); }
DI ull pack2(float v) { ull r; asm("mov.b64 %0, {%1, %1};" : "=l"(r) : "f"(v)); return r; }
DI ull pk(float x, float y) { ull r; asm("mov.b64 %0, {%1, %2};" : "=l"(r) : "f"(x), "f"(y)); return r; }
DI float2 unpk(ull v) { float2 f; asm("mov.b64 {%0, %1}, %2;" : "=f"(f.x), "=f"(f.y) : "l"(v)); return f; }
DI ull lds2(const float* p) { float2 v = *(const float2*)p; return pk(v.x, v.y); }

DI uint32_t smem_u32(const void* p) {
    uint32_t a;
    asm("{ .reg .u64 t; cvta.to.shared.u64 t, %1; cvt.u32.u64 %0, t; }" : "=r"(a) : "l"(p));
    return a;
}
DI void cpasync16(uint32_t saddr, const void* g) {
    asm volatile("cp.async.cg.shared.global [%0], [%1], 16;" :: "r"(saddr), "l"(g));
}
DI void cpcommit() { asm volatile("cp.async.commit_group;" ::: "memory"); }
DI void cpwait0()  { asm volatile("cp.async.wait_group 0;" ::: "memory"); }

DI uint32_t cvt_hi(float x, float y) {
    __half2 h = __floats2half2_rn(x, y);
    return *reinterpret_cast<uint32_t*>(&h);
}

DI void mma16816(float* d, const uint32_t* a, uint32_t b0, uint32_t b1) {
    asm volatile("mma.sync.aligned.m16n8k16.row.col.f32.f16.f16.f32 "
        "{%0,%1,%2,%3}, {%4,%5,%6,%7}, {%8,%9}, {%0,%1,%2,%3};"
        : "+f"(d[0]), "+f"(d[1]), "+f"(d[2]), "+f"(d[3])
        : "r"(a[0]), "r"(a[1]), "r"(a[2]), "r"(a[3]), "r"(b0), "r"(b1));
}

// ---------- pre-kernel: convert basis -> fragment-ordered fp16 global array ----------
extern "C" __global__ void __launch_bounds__(256)
conv_basis(const float* __restrict__ basis)
{
    int s = blockIdx.x * 256 + threadIdx.x;          // 0 .. 13311
    if (s >= B_U2) return;
    int t  = s / STAGE_U2;
    int r  = s - t * STAGE_U2;
    int nt = r >> 5;
    int ln = r & 31;
    int qq = ln & 3;
    int n  = nt * 8 + (ln >> 2);
    uint2 val = make_uint2(0u, 0u);
    if (n < MSZ) {
        int k0 = t * 16 + 2 * qq;
        val.x = cvt_hi(basis[(size_t)k0 * MSZ + n],       basis[(size_t)(k0 + 1) * MSZ + n]);
        val.y = cvt_hi(basis[(size_t)(k0 + 8) * MSZ + n], basis[(size_t)(k0 + 9) * MSZ + n]);
    }
    g_bfrag[s] = val;
}

// ---------- fused kernel: GEMM (fp16 x fp16 single-pass mma.sync, B fully SMEM-resident) + expm ----------
extern "C" __global__ void __launch_bounds__(256, 2)
lie_fused(const float* __restrict__ z, float* __restrict__ out)
{
    extern __shared__ float smem[];
    float* sA = smem;                 // (after GEMM) lie_alg / W working set
    float* sC = smem + SA_FLOATS;     // (after GEMM) A^3 buffer
    const uint2* sB = (const uint2*)smem;   // (during GEMM) whole B: 13312 uint2
    const uint32_t sb_base = smem_u32(smem);

    const int tid = threadIdx.x, lane = tid & 31, w = tid >> 5;
    const int g = lane >> 2, q = lane & 3;
    const size_t rowBase = (size_t)blockIdx.x * 128;
    const size_t row0 = rowBase + w * 16 + g;
    const float* zr0 = z + row0 * ZDIM;
    const float* zr1 = zr0 + 8 * ZDIM;

    // ---- load ENTIRE B into SMEM once (6656 x 16B lines, 26 per thread) ----
    {
        const char* gsrc = (const char*)g_bfrag;
#pragma unroll
        for (int i = 0; i < B_LINES / 256; i++) {       // 26
            int idx = i * 256 + tid;
            cpasync16(sb_base + idx * 16, gsrc + idx * 16);
        }
        cpcommit();
    }

    // prefetch first k16-tile of z fragments (overlaps with B load)
    float2 p00, p01, p10, p11;
    {
        const int kb = 2 * q;
        p00 = *(const float2*)(zr0 + kb);  p01 = *(const float2*)(zr0 + kb + 8);
        p10 = *(const float2*)(zr1 + kb);  p11 = *(const float2*)(zr1 + kb + 8);
    }

    float acc[NT][4];
#pragma unroll
    for (int nt = 0; nt < NT; nt++) { acc[nt][0]=0.f; acc[nt][1]=0.f; acc[nt][2]=0.f; acc[nt][3]=0.f; }

    cpwait0();
    __syncthreads();     // whole B visible; NO barriers inside the main loop

    // ================= GEMM main loop: barrier-free, single pass =================
    for (int t = 0; t < TSTEPS; t++) {
        uint32_t Ah[4];
        Ah[0] = cvt_hi(p00.x, p00.y);   // (row g,   k lo)
        Ah[1] = cvt_hi(p10.x, p10.y);   // (row g+8, k lo)
        Ah[2] = cvt_hi(p01.x, p01.y);   // (row g,   k hi)
        Ah[3] = cvt_hi(p11.x, p11.y);   // (row g+8, k hi)
        if (t + 1 < TSTEPS) {
            const int kb = (t + 1) * 16 + 2 * q;
            p00 = *(const float2*)(zr0 + kb);  p01 = *(const float2*)(zr0 + kb + 8);
            p10 = *(const float2*)(zr1 + kb);  p11 = *(const float2*)(zr1 + kb + 8);
        }

        const uint2* bs = sB + (size_t)t * STAGE_U2 + lane;

        uint2 bb[NT];
#pragma unroll
        for (int j = 0; j < NT; j++) bb[j] = bs[j * 32];   // LDS.64 conflict-free
#pragma unroll
        for (int j = 0; j < NT; j++) mma16816(acc[j], Ah, bb[j].x, bb[j].y);
    }

    __syncthreads();     // all warps done reading B before overwriting region as sA/sC

    // epilogue: fragments -> sA in expm layout
    {
        const int rl0 = w * 16 + g;
#pragma unroll
        for (int nt = 0; nt < NT; nt++) {
            int col = nt * 8 + 2 * q;
            if (col < MSZ) {
                *(float2*)(sA + rl0 * EXP_STR + col)       = make_float2(acc[nt][0], acc[nt][1]);
                *(float2*)(sA + (rl0 + 8) * EXP_STR + col) = make_float2(acc[nt][2], acc[nt][3]);
            }
        }
    }
    __syncthreads();     // lie_alg complete in sA

    // ================= expm: E = I + A + A^2/2 + A^3/6 + A^3*(A/24 + A^2/120 + A^3/720) =====
    {
        const int m  = tid >> 1;       // local matrix 0..127
        const int h  = tid & 1;
        const int i0 = 5 * h;
        const int mb = m * EXP_STR;

        ull acc2[5][5];
#pragma unroll
        for (int ii = 0; ii < 5; ii++)
#pragma unroll
            for (int jp = 0; jp < 5; jp++) acc2[ii][jp] = 0ull;

        // A^2 (own rows) -> acc2
#pragma unroll
        for (int kp = 0; kp < 5; kp++) {
            const int k0 = 2 * kp, k1 = k0 + 1;
            ull r0[5], r1[5];
#pragma unroll
            for (int jp = 0; jp < 5; jp++) {
                r0[jp] = lds2(sA + mb + k0 * 10 + 2 * jp);
                r1[jp] = lds2(sA + mb + k1 * 10 + 2 * jp);
            }
#pragma unroll
            for (int ii = 0; ii < 5; ii++) {
                float2 za2 = *(const float2*)(sA + mb + (i0 + ii) * 10 + k0);
                ull z0 = pack2(za2.x), z1 = pack2(za2.y);
#pragma unroll
                for (int jp = 0; jp < 5; jp++) { fma2(acc2[ii][jp], z0, r0[jp]); fma2(acc2[ii][jp], z1, r1[jp]); }
            }
        }

        // A^3 = A^2 @ A -> sC (two row-groups to bound register pressure)
#pragma unroll
        for (int grp = 0; grp < 2; grp++) {
            const int gbase = grp * 3;
            const int rows  = grp == 0 ? 3 : 2;
            ull a3[3][5];
#pragma unroll
            for (int ii = 0; ii < 3; ii++)
#pragma unroll
                for (int jp = 0; jp < 5; jp++) a3[ii][jp] = 0ull;
#pragma unroll
            for (int kp = 0; kp < 5; kp++) {
                const int k0 = 2 * kp, k1 = k0 + 1;
                ull r0[5], r1[5];
#pragma unroll
                for (int jp = 0; jp < 5; jp++) {
                    r0[jp] = lds2(sA + mb + k0 * 10 + 2 * jp);
                    r1[jp] = lds2(sA + mb + k1 * 10 + 2 * jp);
                }
#pragma unroll
                for (int ii = 0; ii < 3; ii++) {
                    if (ii < rows) {
                        float2 f = unpk(acc2[gbase + ii][kp]);
                        ull z0 = pack2(f.x), z1 = pack2(f.y);
#pragma unroll
                        for (int jp = 0; jp < 5; jp++) { fma2(a3[ii][jp], z0, r0[jp]); fma2(a3[ii][jp], z1, r1[jp]); }
                    }
                }
            }
#pragma unroll
            for (int ii = 0; ii < 3; ii++) {
                if (ii < rows) {
                    const int gi = i0 + gbase + ii;
#pragma unroll
                    for (int jp = 0; jp < 5; jp++)
                        *(float2*)(sC + mb + gi * 10 + 2 * jp) = unpk(a3[ii][jp]);
                }
            }
        }
        __syncthreads();   // all matmul reads of A complete before W overwrite

        // W = A/24 + A^2/120 + A^3/720 -> sA (own rows); U = I + A + A^2/2 + A^3/6 -> acc2
        {
            const float c2 = 0.5f, c3 = 1.f/6.f, c4 = 1.f/24.f, c5 = 1.f/120.f, c6 = 1.f/720.f;
#pragma unroll
            for (int ii = 0; ii < 5; ii++) {
                const int gi = i0 + ii;
#pragma unroll
                for (int jp = 0; jp < 5; jp++) {
                    float2 a  = *(const float2*)(sA + mb + gi * 10 + 2 * jp);
                    float2 b3 = *(const float2*)(sC + mb + gi * 10 + 2 * jp);
                    float2 b2 = unpk(acc2[ii][jp]);
                    float wx = a.x * c4 + b2.x * c5 + b3.x * c6;
                    float wy = a.y * c4 + b2.y * c5 + b3.y * c6;
                    float ux = (gi == 2 * jp     ? 1.f : 0.f) + a.x + b2.x * c2 + b3.x * c3;
                    float uy = (gi == 2 * jp + 1 ? 1.f : 0.f) + a.y + b2.y * c2 + b3.y * c3;
                    *(float2*)(sA + mb + gi * 10 + 2 * jp) = make_float2(wx, wy);
                    acc2[ii][jp] = pk(ux, uy);
                }
            }
        }
        __syncthreads();   // W complete in sA

        // E = U + A^3 @ W  (A^3 from sC own rows; W rows from sA)
#pragma unroll
        for (int kp = 0; kp < 5; kp++) {
            const int k0 = 2 * kp, k1 = k0 + 1;
            ull r0[5], r1[5];
#pragma unroll
            for (int jp = 0; jp < 5; jp++) {
                r0[jp] = lds2(sA + mb + k0 * 10 + 2 * jp);
                r1[jp] = lds2(sA + mb + k1 * 10 + 2 * jp);
            }
#pragma unroll
            for (int ii = 0; ii < 5; ii++) {
                float2 f = *(const float2*)(sC + mb + (i0 + ii) * 10 + k0);
                ull z0 = pack2(f.x), z1 = pack2(f.y);
#pragma unroll
                for (int jp = 0; jp < 5; jp++) { fma2(acc2[ii][jp], z0, r0[jp]); fma2(acc2[ii][jp], z1, r1[jp]); }
            }
        }

        // store own 5 rows (50 contiguous floats)
        float* op = out + (rowBase + m) * MSZ + i0 * 10;
#pragma unroll
        for (int ii = 0; ii < 5; ii++)
#pragma unroll
            for (int jp = 0; jp < 5; jp++)
                *(float2*)(op + ii * 10 + 2 * jp) = unpk(acc2[ii][jp]);
    }
}

// ---------------- launch ----------------
extern "C" void kernel_launch(void* const* d_in, const int* in_sizes, int n_in,
                              void* d_out, int out_size)
{
    const float* z     = (const float*)d_in[0];   // [B, 512]
    const float* basis = (const float*)d_in[1];   // [512, 10, 10]
    float* out = (float*)d_out;                   // [B, 10, 10]

    int B = in_sizes[0] / ZDIM;                   // 131072

    cudaFuncSetAttribute(lie_fused, cudaFuncAttributeMaxDynamicSharedMemorySize, SMEM_DYN);

    conv_basis<<<52, 256>>>(basis);               // 13312 fragment slots
    lie_fused<<<B / 128, 256, SMEM_DYN>>>(z, out);
}

// round 15
// speedup vs baseline: 1.5841x; 1.0917x over previous
#include <cuda_runtime.h>
#include <cuda_fp16.h>
#include <cstdint>
#include <cstddef>

#define DI __device__ __forceinline__
typedef unsigned long long ull;

static constexpr int ZDIM = 512;
static constexpr int MSZ  = 100;
static constexpr int NT   = 13;                      // n8 tiles (104 >= 100)
static constexpr int TSTEPS = ZDIM / 16;             // 32 k16-tiles -> 16 t-pairs
static constexpr int EXP_STR   = 106;                // even (LDS.64 aligned), conflict-free residues
static constexpr int SA_FLOATS = 128 * EXP_STR;      // 13568 floats = 54272 B
static constexpr int SMEM_DYN  = 2 * SA_FLOATS * 4;  // 108544 B (>= whole B: 106496 B)
static constexpr int STAGE_U2  = NT * 32;            // 416 uint2 per k16 stage
static constexpr int B_U2      = TSTEPS * STAGE_U2;  // 13312 uint2 = 106496 B
static constexpr int B_LINES   = B_U2 / 2;           // 6656 x 16B cp.async lines

// basis fragments (fp16), fragment-ordered: [t][nt][lane] = (b0h, b1h)
__device__ uint2 g_bfrag[B_U2];                      // 106,496 B (L2-resident)

DI void fma2(ull& d, ull a, ull b) { asm("fma.rn.f32x2 %0, %1, %2, %0;" : "+l"(d) : "l"(a), "l"(b)); }
DI ull pack2(float v) { ull r; asm("mov.b64 %0, {%1, %1};" : "=l"(r) : "f"(v)); return r; }
DI ull pk(float x, float y) { ull r; asm("mov.b64 %0, {%1, %2};" : "=l"(r) : "f"(x), "f"(y)); return r; }
DI float2 unpk(ull v) { float2 f; asm("mov.b64 {%0, %1}, %2;" : "=f"(f.x), "=f"(f.y) : "l"(v)); return f; }
DI ull lds2(const float* p) { float2 v = *(const float2*)p; return pk(v.x, v.y); }

DI uint32_t smem_u32(const void* p) {
    uint32_t a;
    asm("{ .reg .u64 t; cvta.to.shared.u64 t, %1; cvt.u32.u64 %0, t; }" : "=r"(a) : "l"(p));
    return a;
}
DI void cpasync16(uint32_t saddr, const void* g) {
    asm volatile("cp.async.cg.shared.global [%0], [%1], 16;" :: "r"(saddr), "l"(g));
}
DI void cpcommit() { asm volatile("cp.async.commit_group;" ::: "memory"); }
DI void cpwait0()  { asm volatile("cp.async.wait_group 0;" ::: "memory"); }

DI uint32_t cvt_hi(float x, float y) {
    __half2 h = __floats2half2_rn(x, y);
    return *reinterpret_cast<uint32_t*>(&h);
}

DI void mma16816(float* d, const uint32_t* a, uint32_t b0, uint32_t b1) {
    asm volatile("mma.sync.aligned.m16n8k16.row.col.f32.f16.f16.f32 "
        "{%0,%1,%2,%3}, {%4,%5,%6,%7}, {%8,%9}, {%0,%1,%2,%3};"
        : "+f"(d[0]), "+f"(d[1]), "+f"(d[2]), "+f"(d[3])
        : "r"(a[0]), "r"(a[1]), "r"(a[2]), "r"(a[3]), "r"(b0), "r"(b1));
}

// fetch (lo,hi) registers from src lane, select by parity
DI uint32_t pick(uint32_t lo, uint32_t hi, int rsel, int src) {
    uint32_t t0 = __shfl_sync(0xffffffffu, lo, src);
    uint32_t t1 = __shfl_sync(0xffffffffu, hi, src);
    return rsel ? t1 : t0;
}

// ---------- pre-kernel: convert basis -> fragment-ordered fp16 global array ----------
extern "C" __global__ void __launch_bounds__(256)
conv_basis(const float* __restrict__ basis)
{
    int s = blockIdx.x * 256 + threadIdx.x;          // 0 .. 13311
    if (s >= B_U2) return;
    int t  = s / STAGE_U2;
    int r  = s - t * STAGE_U2;
    int nt = r >> 5;
    int ln = r & 31;
    int qq = ln & 3;
    int n  = nt * 8 + (ln >> 2);
    uint2 val = make_uint2(0u, 0u);
    if (n < MSZ) {
        int k0 = t * 16 + 2 * qq;
        val.x = cvt_hi(basis[(size_t)k0 * MSZ + n],       basis[(size_t)(k0 + 1) * MSZ + n]);
        val.y = cvt_hi(basis[(size_t)(k0 + 8) * MSZ + n], basis[(size_t)(k0 + 9) * MSZ + n]);
    }
    g_bfrag[s] = val;
}

// ---------- fused kernel: GEMM (fp16 mma.sync, B SMEM-resident, t-pair z loads + shfl) + expm ----------
extern "C" __global__ void __launch_bounds__(256, 2)
lie_fused(const float* __restrict__ z, float* __restrict__ out)
{
    extern __shared__ float smem[];
    float* sA = smem;                 // (after GEMM) lie_alg / W working set
    float* sC = smem + SA_FLOATS;     // (after GEMM) A^3 buffer
    const uint2* sB = (const uint2*)smem;   // (during GEMM) whole B: 13312 uint2
    const uint32_t sb_base = smem_u32(smem);

    const int tid = threadIdx.x, lane = tid & 31, w = tid >> 5;
    const int g = lane >> 2, q = lane & 3;
    const int src  = (lane & 0x1C) | (q >> 1);   // 4g + q/2
    const int src2 = src + 2;
    const int rsel = q & 1;
    const size_t rowBase = (size_t)blockIdx.x * 128;
    const size_t row0 = rowBase + w * 16 + g;
    const float* zr0 = z + row0 * ZDIM;          // row g
    const float* zr1 = zr0 + 8 * ZDIM;           // row g+8

    // ---- load ENTIRE B into SMEM once (6656 x 16B lines, 26 per thread) ----
    {
        const char* gsrc = (const char*)g_bfrag;
#pragma unroll
        for (int i = 0; i < B_LINES / 256; i++) {       // 26
            int idx = i * 256 + tid;
            cpasync16(sb_base + idx * 16, gsrc + idx * 16);
        }
        cpcommit();
    }

    // ---- prefetch z t-pair 0 and convert ----
    // per pair tp: F0 = (row g, k 32tp+4q..+3), F1 = +16; G0/G1 = row g+8
    uint32_t u[4], v[4];    // u: row g   — u0:(4q,4q+1) u1:(4q+2,4q+3) u2:(16+4q..) u3:(16+4q+2..)
    {
        float4 F0 = *(const float4*)(zr0 + 4 * q);
        float4 F1 = *(const float4*)(zr0 + 16 + 4 * q);
        float4 G0 = *(const float4*)(zr1 + 4 * q);
        float4 G1 = *(const float4*)(zr1 + 16 + 4 * q);
        u[0] = cvt_hi(F0.x, F0.y); u[1] = cvt_hi(F0.z, F0.w);
        u[2] = cvt_hi(F1.x, F1.y); u[3] = cvt_hi(F1.z, F1.w);
        v[0] = cvt_hi(G0.x, G0.y); v[1] = cvt_hi(G0.z, G0.w);
        v[2] = cvt_hi(G1.x, G1.y); v[3] = cvt_hi(G1.z, G1.w);
    }

    float acc[NT][4];
#pragma unroll
    for (int nt = 0; nt < NT; nt++) { acc[nt][0]=0.f; acc[nt][1]=0.f; acc[nt][2]=0.f; acc[nt][3]=0.f; }

    cpwait0();
    __syncthreads();     // whole B visible; NO barriers inside the main loop

    // ================= GEMM main loop over 16 t-pairs: barrier-free =================
    for (int tp = 0; tp < TSTEPS / 2; tp++) {
        // issue loads for next pair (float4 temps stay in flight through the MMA section)
        float4 F0, F1, G0, G1;
        const bool more = (tp + 1 < TSTEPS / 2);
        if (more) {
            const float* a0p = zr0 + (tp + 1) * 32 + 4 * q;
            const float* a1p = zr1 + (tp + 1) * 32 + 4 * q;
            F0 = *(const float4*)(a0p);      F1 = *(const float4*)(a0p + 16);
            G0 = *(const float4*)(a1p);      G1 = *(const float4*)(a1p + 16);
        }

        // ---- t0 = 2*tp ----
        {
            uint32_t Ah[4];
            Ah[0] = pick(u[0], u[1], rsel, src);    // (g,   2q..2q+1)
            Ah[1] = pick(v[0], v[1], rsel, src);    // (g+8, 2q..2q+1)
            Ah[2] = pick(u[0], u[1], rsel, src2);   // (g,   2q+8..2q+9)
            Ah[3] = pick(v[0], v[1], rsel, src2);   // (g+8, 2q+8..2q+9)
            const uint2* bs = sB + (size_t)(2 * tp) * STAGE_U2 + lane;
            uint2 bb[NT];
#pragma unroll
            for (int j = 0; j < NT; j++) bb[j] = bs[j * 32];
#pragma unroll
            for (int j = 0; j < NT; j++) mma16816(acc[j], Ah, bb[j].x, bb[j].y);
        }
        // ---- t1 = 2*tp+1 ----
        {
            uint32_t Ah[4];
            Ah[0] = pick(u[2], u[3], rsel, src);
            Ah[1] = pick(v[2], v[3], rsel, src);
            Ah[2] = pick(u[2], u[3], rsel, src2);
            Ah[3] = pick(v[2], v[3], rsel, src2);
            const uint2* bs = sB + (size_t)(2 * tp + 1) * STAGE_U2 + lane;
            uint2 bb[NT];
#pragma unroll
            for (int j = 0; j < NT; j++) bb[j] = bs[j * 32];
#pragma unroll
            for (int j = 0; j < NT; j++) mma16816(acc[j], Ah, bb[j].x, bb[j].y);
        }

        // convert prefetched floats for next pair
        if (more) {
            u[0] = cvt_hi(F0.x, F0.y); u[1] = cvt_hi(F0.z, F0.w);
            u[2] = cvt_hi(F1.x, F1.y); u[3] = cvt_hi(F1.z, F1.w);
            v[0] = cvt_hi(G0.x, G0.y); v[1] = cvt_hi(G0.z, G0.w);
            v[2] = cvt_hi(G1.x, G1.y); v[3] = cvt_hi(G1.z, G1.w);
        }
    }

    __syncthreads();     // all warps done reading B before overwriting region as sA/sC

    // epilogue: fragments -> sA in expm layout
    {
        const int rl0 = w * 16 + g;
#pragma unroll
        for (int nt = 0; nt < NT; nt++) {
            int col = nt * 8 + 2 * q;
            if (col < MSZ) {
                *(float2*)(sA + rl0 * EXP_STR + col)       = make_float2(acc[nt][0], acc[nt][1]);
                *(float2*)(sA + (rl0 + 8) * EXP_STR + col) = make_float2(acc[nt][2], acc[nt][3]);
            }
        }
    }
    __syncthreads();     // lie_alg complete in sA

    // ================= expm: E = I + A + A^2/2 + A^3/6 + A^3*(A/24 + A^2/120 + A^3/720) =====
    {
        const int m  = tid >> 1;       // local matrix 0..127
        const int h  = tid & 1;
        const int i0 = 5 * h;
        const int mb = m * EXP_STR;

        ull acc2[5][5];
#pragma unroll
        for (int ii = 0; ii < 5; ii++)
#pragma unroll
            for (int jp = 0; jp < 5; jp++) acc2[ii][jp] = 0ull;

        // A^2 (own rows) -> acc2
#pragma unroll
        for (int kp = 0; kp < 5; kp++) {
            const int k0 = 2 * kp, k1 = k0 + 1;
            ull r0[5], r1[5];
#pragma unroll
            for (int jp = 0; jp < 5; jp++) {
                r0[jp] = lds2(sA + mb + k0 * 10 + 2 * jp);
                r1[jp] = lds2(sA + mb + k1 * 10 + 2 * jp);
            }
#pragma unroll
            for (int ii = 0; ii < 5; ii++) {
                float2 za2 = *(const float2*)(sA + mb + (i0 + ii) * 10 + k0);
                ull z0 = pack2(za2.x), z1 = pack2(za2.y);
#pragma unroll
                for (int jp = 0; jp < 5; jp++) { fma2(acc2[ii][jp], z0, r0[jp]); fma2(acc2[ii][jp], z1, r1[jp]); }
            }
        }

        // A^3 = A^2 @ A -> sC (two row-groups to bound register pressure)
#pragma unroll
        for (int grp = 0; grp < 2; grp++) {
            const int gbase = grp * 3;
            const int rows  = grp == 0 ? 3 : 2;
            ull a3[3][5];
#pragma unroll
            for (int ii = 0; ii < 3; ii++)
#pragma unroll
                for (int jp = 0; jp < 5; jp++) a3[ii][jp] = 0ull;
#pragma unroll
            for (int kp = 0; kp < 5; kp++) {
                const int k0 = 2 * kp, k1 = k0 + 1;
                ull r0[5], r1[5];
#pragma unroll
                for (int jp = 0; jp < 5; jp++) {
                    r0[jp] = lds2(sA + mb + k0 * 10 + 2 * jp);
                    r1[jp] = lds2(sA + mb + k1 * 10 + 2 * jp);
                }
#pragma unroll
                for (int ii = 0; ii < 3; ii++) {
                    if (ii < rows) {
                        float2 f = unpk(acc2[gbase + ii][kp]);
                        ull z0 = pack2(f.x), z1 = pack2(f.y);
#pragma unroll
                        for (int jp = 0; jp < 5; jp++) { fma2(a3[ii][jp], z0, r0[jp]); fma2(a3[ii][jp], z1, r1[jp]); }
                    }
                }
            }
#pragma unroll
            for (int ii = 0; ii < 3; ii++) {
                if (ii < rows) {
                    const int gi = i0 + gbase + ii;
#pragma unroll
                    for (int jp = 0; jp < 5; jp++)
                        *(float2*)(sC + mb + gi * 10 + 2 * jp) = unpk(a3[ii][jp]);
                }
            }
        }
        __syncthreads();   // all matmul reads of A complete before W overwrite

        // W = A/24 + A^2/120 + A^3/720 -> sA (own rows); U = I + A + A^2/2 + A^3/6 -> acc2
        {
            const float c2 = 0.5f, c3 = 1.f/6.f, c4 = 1.f/24.f, c5 = 1.f/120.f, c6 = 1.f/720.f;
#pragma unroll
            for (int ii = 0; ii < 5; ii++) {
                const int gi = i0 + ii;
#pragma unroll
                for (int jp = 0; jp < 5; jp++) {
                    float2 a  = *(const float2*)(sA + mb + gi * 10 + 2 * jp);
                    float2 b3 = *(const float2*)(sC + mb + gi * 10 + 2 * jp);
                    float2 b2 = unpk(acc2[ii][jp]);
                    float wx = a.x * c4 + b2.x * c5 + b3.x * c6;
                    float wy = a.y * c4 + b2.y * c5 + b3.y * c6;
                    float ux = (gi == 2 * jp     ? 1.f : 0.f) + a.x + b2.x * c2 + b3.x * c3;
                    float uy = (gi == 2 * jp + 1 ? 1.f : 0.f) + a.y + b2.y * c2 + b3.y * c3;
                    *(float2*)(sA + mb + gi * 10 + 2 * jp) = make_float2(wx, wy);
                    acc2[ii][jp] = pk(ux, uy);
                }
            }
        }
        __syncthreads();   // W complete in sA

        // E = U + A^3 @ W  (A^3 from sC own rows; W rows from sA)
#pragma unroll
        for (int kp = 0; kp < 5; kp++) {
            const int k0 = 2 * kp, k1 = k0 + 1;
            ull r0[5], r1[5];
#pragma unroll
            for (int jp = 0; jp < 5; jp++) {
                r0[jp] = lds2(sA + mb + k0 * 10 + 2 * jp);
                r1[jp] = lds2(sA + mb + k1 * 10 + 2 * jp);
            }
#pragma unroll
            for (int ii = 0; ii < 5; ii++) {
                float2 f = *(const float2*)(sC + mb + (i0 + ii) * 10 + k0);
                ull z0 = pack2(f.x), z1 = pack2(f.y);
#pragma unroll
                for (int jp = 0; jp < 5; jp++) { fma2(acc2[ii][jp], z0, r0[jp]); fma2(acc2[ii][jp], z1, r1[jp]); }
            }
        }

        // store own 5 rows (50 contiguous floats)
        float* op = out + (rowBase + m) * MSZ + i0 * 10;
#pragma unroll
        for (int ii = 0; ii < 5; ii++)
#pragma unroll
            for (int jp = 0; jp < 5; jp++)
                *(float2*)(op + ii * 10 + 2 * jp) = unpk(acc2[ii][jp]);
    }
}

// ---------------- launch ----------------
extern "C" void kernel_launch(void* const* d_in, const int* in_sizes, int n_in,
                              void* d_out, int out_size)
{
    const float* z     = (const float*)d_in[0];   // [B, 512]
    const float* basis = (const float*)d_in[1];   // [512, 10, 10]
    float* out = (float*)d_out;                   // [B, 10, 10]

    int B = in_sizes[0] / ZDIM;                   // 131072

    cudaFuncSetAttribute(lie_fused, cudaFuncAttributeMaxDynamicSharedMemorySize, SMEM_DYN);

    conv_basis<<<52, 256>>>(basis);               // 13312 fragment slots
    lie_fused<<<B / 128, 256, SMEM_DYN>>>(z, out);
}

// round 16
// speedup vs baseline: 1.8708x; 1.1810x over previous
#include <cuda_runtime.h>
#include <cuda_fp16.h>
#include <cstdint>
#include <cstddef>

#define DI __device__ __forceinline__
typedef unsigned long long ull;

static constexpr int ZDIM = 512;
static constexpr int MSZ  = 100;
static constexpr int NT   = 13;                      // n8 tiles (104 >= 100)
static constexpr int TSTEPS = ZDIM / 16;             // 32 k16-tiles -> 16 t-pairs
static constexpr int EXP_STR   = 106;                // even (LDS.64 aligned), conflict-free residues
static constexpr int SA_FLOATS = 128 * EXP_STR;      // 13568 floats = 54272 B
static constexpr int SMEM_DYN  = 2 * SA_FLOATS * 4;  // 108544 B (>= whole B: 106496 B)
static constexpr int STAGE_U2  = NT * 32;            // 416 uint2 per k16 stage
static constexpr int B_U2      = TSTEPS * STAGE_U2;  // 13312 uint2 = 106496 B
static constexpr int B_LINES   = B_U2 / 2;           // 6656 x 16B cp.async lines

// basis fragments (fp16), fragment-ordered: [t][nt][lane] = (b0h, b1h)
__device__ uint2 g_bfrag[B_U2];                      // 106,496 B (L2-resident)

DI void fma2(ull& d, ull a, ull b) { asm("fma.rn.f32x2 %0, %1, %2, %0;" : "+l"(d) : "l"(a), "l"(b)); }
DI ull pack2(float v) { ull r; asm("mov.b64 %0, {%1, %1};" : "=l"(r) : "f"(v)); return r; }
DI ull pk(float x, float y) { ull r; asm("mov.b64 %0, {%1, %2};" : "=l"(r) : "f"(x), "f"(y)); return r; }
DI float2 unpk(ull v) { float2 f; asm("mov.b64 {%0, %1}, %2;" : "=f"(f.x), "=f"(f.y) : "l"(v)); return f; }
DI ull lds2(const float* p) { float2 v = *(const float2*)p; return pk(v.x, v.y); }

DI uint32_t smem_u32(const void* p) {
    uint32_t a;
    asm("{ .reg .u64 t; cvta.to.shared.u64 t, %1; cvt.u32.u64 %0, t; }" : "=r"(a) : "l"(p));
    return a;
}
DI void cpasync16(uint32_t saddr, const void* g) {
    asm volatile("cp.async.cg.shared.global [%0], [%1], 16;" :: "r"(saddr), "l"(g));
}
DI void cpcommit() { asm volatile("cp.async.commit_group;" ::: "memory"); }
DI void cpwait0()  { asm volatile("cp.async.wait_group 0;" ::: "memory"); }

DI uint32_t cvt_hi(float x, float y) {
    __half2 h = __floats2half2_rn(x, y);
    return *reinterpret_cast<uint32_t*>(&h);
}

DI void mma16816(float* d, const uint32_t* a, uint32_t b0, uint32_t b1) {
    asm volatile("mma.sync.aligned.m16n8k16.row.col.f32.f16.f16.f32 "
        "{%0,%1,%2,%3}, {%4,%5,%6,%7}, {%8,%9}, {%0,%1,%2,%3};"
        : "+f"(d[0]), "+f"(d[1]), "+f"(d[2]), "+f"(d[3])
        : "r"(a[0]), "r"(a[1]), "r"(a[2]), "r"(a[3]), "r"(b0), "r"(b1));
}

// fetch (lo,hi) registers from src lane, select by parity
DI uint32_t pick(uint32_t lo, uint32_t hi, int rsel, int src) {
    uint32_t t0 = __shfl_sync(0xffffffffu, lo, src);
    uint32_t t1 = __shfl_sync(0xffffffffu, hi, src);
    return rsel ? t1 : t0;
}

// ---------- pre-kernel: convert basis -> fragment-ordered fp16 global array ----------
extern "C" __global__ void __launch_bounds__(256)
conv_basis(const float* __restrict__ basis)
{
    int s = blockIdx.x * 256 + threadIdx.x;          // 0 .. 13311
    if (s >= B_U2) return;
    int t  = s / STAGE_U2;
    int r  = s - t * STAGE_U2;
    int nt = r >> 5;
    int ln = r & 31;
    int qq = ln & 3;
    int n  = nt * 8 + (ln >> 2);
    uint2 val = make_uint2(0u, 0u);
    if (n < MSZ) {
        int k0 = t * 16 + 2 * qq;
        val.x = cvt_hi(basis[(size_t)k0 * MSZ + n],       basis[(size_t)(k0 + 1) * MSZ + n]);
        val.y = cvt_hi(basis[(size_t)(k0 + 8) * MSZ + n], basis[(size_t)(k0 + 9) * MSZ + n]);
    }
    g_bfrag[s] = val;
}

// ---------- fused kernel: GEMM (fp16 mma.sync, B SMEM-resident, t-pair z loads + shfl)
//            + expm degree-4: E = I + A + A^2*(I/2 + A/6 + A^2/24) ----------
extern "C" __global__ void __launch_bounds__(256, 2)
lie_fused(const float* __restrict__ z, float* __restrict__ out)
{
    extern __shared__ float smem[];
    float* sA = smem;                 // (after GEMM) lie_alg A (never overwritten)
    float* sC = smem + SA_FLOATS;     // (after GEMM) M buffer
    const uint2* sB = (const uint2*)smem;   // (during GEMM) whole B: 13312 uint2
    const uint32_t sb_base = smem_u32(smem);

    const int tid = threadIdx.x, lane = tid & 31, w = tid >> 5;
    const int g = lane >> 2, q = lane & 3;
    const int src  = (lane & 0x1C) | (q >> 1);   // 4g + q/2
    const int src2 = src + 2;
    const int rsel = q & 1;
    const size_t rowBase = (size_t)blockIdx.x * 128;
    const size_t row0 = rowBase + w * 16 + g;
    const float* zr0 = z + row0 * ZDIM;          // row g
    const float* zr1 = zr0 + 8 * ZDIM;           // row g+8

    // ---- load ENTIRE B into SMEM once (6656 x 16B lines, 26 per thread) ----
    {
        const char* gsrc = (const char*)g_bfrag;
#pragma unroll
        for (int i = 0; i < B_LINES / 256; i++) {       // 26
            int idx = i * 256 + tid;
            cpasync16(sb_base + idx * 16, gsrc + idx * 16);
        }
        cpcommit();
    }

    // ---- prefetch z t-pair 0 and convert ----
    uint32_t u[4], v[4];
    {
        float4 F0 = *(const float4*)(zr0 + 4 * q);
        float4 F1 = *(const float4*)(zr0 + 16 + 4 * q);
        float4 G0 = *(const float4*)(zr1 + 4 * q);
        float4 G1 = *(const float4*)(zr1 + 16 + 4 * q);
        u[0] = cvt_hi(F0.x, F0.y); u[1] = cvt_hi(F0.z, F0.w);
        u[2] = cvt_hi(F1.x, F1.y); u[3] = cvt_hi(F1.z, F1.w);
        v[0] = cvt_hi(G0.x, G0.y); v[1] = cvt_hi(G0.z, G0.w);
        v[2] = cvt_hi(G1.x, G1.y); v[3] = cvt_hi(G1.z, G1.w);
    }

    float acc[NT][4];
#pragma unroll
    for (int nt = 0; nt < NT; nt++) { acc[nt][0]=0.f; acc[nt][1]=0.f; acc[nt][2]=0.f; acc[nt][3]=0.f; }

    cpwait0();
    __syncthreads();     // whole B visible; NO barriers inside the main loop

    // ================= GEMM main loop over 16 t-pairs: barrier-free =================
    for (int tp = 0; tp < TSTEPS / 2; tp++) {
        float4 F0, F1, G0, G1;
        const bool more = (tp + 1 < TSTEPS / 2);
        if (more) {
            const float* a0p = zr0 + (tp + 1) * 32 + 4 * q;
            const float* a1p = zr1 + (tp + 1) * 32 + 4 * q;
            F0 = *(const float4*)(a0p);      F1 = *(const float4*)(a0p + 16);
            G0 = *(const float4*)(a1p);      G1 = *(const float4*)(a1p + 16);
        }

        // ---- t0 = 2*tp ----
        {
            uint32_t Ah[4];
            Ah[0] = pick(u[0], u[1], rsel, src);
            Ah[1] = pick(v[0], v[1], rsel, src);
            Ah[2] = pick(u[0], u[1], rsel, src2);
            Ah[3] = pick(v[0], v[1], rsel, src2);
            const uint2* bs = sB + (size_t)(2 * tp) * STAGE_U2 + lane;
            uint2 bb[NT];
#pragma unroll
            for (int j = 0; j < NT; j++) bb[j] = bs[j * 32];
#pragma unroll
            for (int j = 0; j < NT; j++) mma16816(acc[j], Ah, bb[j].x, bb[j].y);
        }
        // ---- t1 = 2*tp+1 ----
        {
            uint32_t Ah[4];
            Ah[0] = pick(u[2], u[3], rsel, src);
            Ah[1] = pick(v[2], v[3], rsel, src);
            Ah[2] = pick(u[2], u[3], rsel, src2);
            Ah[3] = pick(v[2], v[3], rsel, src2);
            const uint2* bs = sB + (size_t)(2 * tp + 1) * STAGE_U2 + lane;
            uint2 bb[NT];
#pragma unroll
            for (int j = 0; j < NT; j++) bb[j] = bs[j * 32];
#pragma unroll
            for (int j = 0; j < NT; j++) mma16816(acc[j], Ah, bb[j].x, bb[j].y);
        }

        if (more) {
            u[0] = cvt_hi(F0.x, F0.y); u[1] = cvt_hi(F0.z, F0.w);
            u[2] = cvt_hi(F1.x, F1.y); u[3] = cvt_hi(F1.z, F1.w);
            v[0] = cvt_hi(G0.x, G0.y); v[1] = cvt_hi(G0.z, G0.w);
            v[2] = cvt_hi(G1.x, G1.y); v[3] = cvt_hi(G1.z, G1.w);
        }
    }

    __syncthreads();     // all warps done reading B before overwriting region as sA/sC

    // epilogue: fragments -> sA in expm layout
    {
        const int rl0 = w * 16 + g;
#pragma unroll
        for (int nt = 0; nt < NT; nt++) {
            int col = nt * 8 + 2 * q;
            if (col < MSZ) {
                *(float2*)(sA + rl0 * EXP_STR + col)       = make_float2(acc[nt][0], acc[nt][1]);
                *(float2*)(sA + (rl0 + 8) * EXP_STR + col) = make_float2(acc[nt][2], acc[nt][3]);
            }
        }
    }
    __syncthreads();     // lie_alg complete in sA

    // ================= expm degree-4: E = I + A + A^2 @ M,  M = I/2 + A/6 + A^2/24 ==========
    {
        const int m  = tid >> 1;       // local matrix 0..127
        const int h  = tid & 1;
        const int i0 = 5 * h;
        const int mb = m * EXP_STR;

        ull acc2[5][5];
#pragma unroll
        for (int ii = 0; ii < 5; ii++)
#pragma unroll
            for (int jp = 0; jp < 5; jp++) acc2[ii][jp] = 0ull;

        // A^2 (own rows) -> acc2
#pragma unroll
        for (int kp = 0; kp < 5; kp++) {
            const int k0 = 2 * kp, k1 = k0 + 1;
            ull r0[5], r1[5];
#pragma unroll
            for (int jp = 0; jp < 5; jp++) {
                r0[jp] = lds2(sA + mb + k0 * 10 + 2 * jp);
                r1[jp] = lds2(sA + mb + k1 * 10 + 2 * jp);
            }
#pragma unroll
            for (int ii = 0; ii < 5; ii++) {
                float2 za2 = *(const float2*)(sA + mb + (i0 + ii) * 10 + k0);
                ull z0 = pack2(za2.x), z1 = pack2(za2.y);
#pragma unroll
                for (int jp = 0; jp < 5; jp++) { fma2(acc2[ii][jp], z0, r0[jp]); fma2(acc2[ii][jp], z1, r1[jp]); }
            }
        }

        // M = I/2 + A/6 + A^2/24 -> sC (own rows); sA (=A) stays intact
        {
            const float c1 = 1.f / 6.f, cM = 1.f / 24.f;
#pragma unroll
            for (int ii = 0; ii < 5; ii++) {
                const int gi = i0 + ii;
#pragma unroll
                for (int jp = 0; jp < 5; jp++) {
                    float2 a  = *(const float2*)(sA + mb + gi * 10 + 2 * jp);
                    float2 b2 = unpk(acc2[ii][jp]);
                    float mx = (gi == 2 * jp     ? 0.5f : 0.f) + a.x * c1 + b2.x * cM;
                    float my = (gi == 2 * jp + 1 ? 0.5f : 0.f) + a.y * c1 + b2.y * cM;
                    *(float2*)(sC + mb + gi * 10 + 2 * jp) = make_float2(mx, my);
                }
            }
        }
        __syncthreads();   // M complete in sC (pair partner's rows needed below)

        // E = I + A + A^2 @ M  -> out, two row-groups to bound register pressure
#pragma unroll
        for (int grp = 0; grp < 2; grp++) {
            const int gbase = grp * 3;
            const int rows  = grp == 0 ? 3 : 2;
            ull ae[3][5];
            // init ae = I + A (own rows)
#pragma unroll
            for (int ii = 0; ii < 3; ii++) {
                if (ii < rows) {
                    const int gi = i0 + gbase + ii;
#pragma unroll
                    for (int jp = 0; jp < 5; jp++) {
                        float2 a = *(const float2*)(sA + mb + gi * 10 + 2 * jp);
                        float ex = (gi == 2 * jp     ? 1.f : 0.f) + a.x;
                        float ey = (gi == 2 * jp + 1 ? 1.f : 0.f) + a.y;
                        ae[ii][jp] = pk(ex, ey);
                    }
                }
            }
#pragma unroll
            for (int kp = 0; kp < 5; kp++) {
                const int k0 = 2 * kp, k1 = k0 + 1;
                ull r0[5], r1[5];
#pragma unroll
                for (int jp = 0; jp < 5; jp++) {
                    r0[jp] = lds2(sC + mb + k0 * 10 + 2 * jp);
                    r1[jp] = lds2(sC + mb + k1 * 10 + 2 * jp);
                }
#pragma unroll
                for (int ii = 0; ii < 3; ii++) {
                    if (ii < rows) {
                        float2 f = unpk(acc2[gbase + ii][kp]);
                        ull z0 = pack2(f.x), z1 = pack2(f.y);
#pragma unroll
                        for (int jp = 0; jp < 5; jp++) { fma2(ae[ii][jp], z0, r0[jp]); fma2(ae[ii][jp], z1, r1[jp]); }
                    }
                }
            }
            // store this group's rows (30 or 20 contiguous floats)
            float* op = out + (rowBase + m) * MSZ + (i0 + gbase) * 10;
#pragma unroll
            for (int ii = 0; ii < 3; ii++) {
                if (ii < rows) {
#pragma unroll
                    for (int jp = 0; jp < 5; jp++)
                        *(float2*)(op + ii * 10 + 2 * jp) = unpk(ae[ii][jp]);
                }
            }
        }
    }
}

// ---------------- launch ----------------
extern "C" void kernel_launch(void* const* d_in, const int* in_sizes, int n_in,
                              void* d_out, int out_size)
{
    const float* z     = (const float*)d_in[0];   // [B, 512]
    const float* basis = (const float*)d_in[1];   // [512, 10, 10]
    float* out = (float*)d_out;                   // [B, 10, 10]

    int B = in_sizes[0] / ZDIM;                   // 131072

    cudaFuncSetAttribute(lie_fused, cudaFuncAttributeMaxDynamicSharedMemorySize, SMEM_DYN);

    conv_basis<<<52, 256>>>(basis);               // 13312 fragment slots
    lie_fused<<<B / 128, 256, SMEM_DYN>>>(z, out);
}

// round 17
// speedup vs baseline: 1.8713x; 1.0003x over previous
#include <cuda_runtime.h>
#include <cuda_fp16.h>
#include <cstdint>
#include <cstddef>

#define DI __device__ __forceinline__
typedef unsigned long long ull;

static constexpr int ZDIM = 512;
static constexpr int MSZ  = 100;
static constexpr int NT   = 13;                      // n8 tiles (104 >= 100)
static constexpr int TSTEPS = ZDIM / 16;             // 32 k16-tiles -> 16 t-pairs
static constexpr int EXP_STR   = 106;                // even (LDS.64 aligned), conflict-free residues
static constexpr int SA_FLOATS = 128 * EXP_STR;      // 13568 floats = 54272 B
static constexpr int SMEM_DYN  = 2 * SA_FLOATS * 4;  // 108544 B (>= whole B: 106496 B)
static constexpr int STAGE_U2  = NT * 32;            // 416 uint2 per k16 stage
static constexpr int B_U2      = TSTEPS * STAGE_U2;  // 13312 uint2 = 106496 B
static constexpr int B_LINES   = B_U2 / 2;           // 6656 x 16B cp.async lines

// basis fragments (fp16), fragment-ordered: [t][nt][lane] = (b0h, b1h)
__device__ uint2 g_bfrag[B_U2];                      // 106,496 B (L2-resident)

DI void fma2(ull& d, ull a, ull b) { asm("fma.rn.f32x2 %0, %1, %2, %0;" : "+l"(d) : "l"(a), "l"(b)); }
DI ull pack2(float v) { ull r; asm("mov.b64 %0, {%1, %1};" : "=l"(r) : "f"(v)); return r; }
DI ull pk(float x, float y) { ull r; asm("mov.b64 %0, {%1, %2};" : "=l"(r) : "f"(x), "f"(y)); return r; }
DI float2 unpk(ull v) { float2 f; asm("mov.b64 {%0, %1}, %2;" : "=f"(f.x), "=f"(f.y) : "l"(v)); return f; }
DI ull lds2(const float* p) { float2 v = *(const float2*)p; return pk(v.x, v.y); }

DI uint32_t smem_u32(const void* p) {
    uint32_t a;
    asm("{ .reg .u64 t; cvta.to.shared.u64 t, %1; cvt.u32.u64 %0, t; }" : "=r"(a) : "l"(p));
    return a;
}
DI void cpasync16(uint32_t saddr, const void* g) {
    asm volatile("cp.async.cg.shared.global [%0], [%1], 16;" :: "r"(saddr), "l"(g));
}
DI void cpcommit() { asm volatile("cp.async.commit_group;" ::: "memory"); }
DI void cpwait0()  { asm volatile("cp.async.wait_group 0;" ::: "memory"); }

DI uint32_t cvt_hi(float x, float y) {
    __half2 h = __floats2half2_rn(x, y);
    return *reinterpret_cast<uint32_t*>(&h);
}

DI void mma16816(float* d, const uint32_t* a, uint32_t b0, uint32_t b1) {
    asm volatile("mma.sync.aligned.m16n8k16.row.col.f32.f16.f16.f32 "
        "{%0,%1,%2,%3}, {%4,%5,%6,%7}, {%8,%9}, {%0,%1,%2,%3};"
        : "+f"(d[0]), "+f"(d[1]), "+f"(d[2]), "+f"(d[3])
        : "r"(a[0]), "r"(a[1]), "r"(a[2]), "r"(a[3]), "r"(b0), "r"(b1));
}

// fetch (lo,hi) registers from src lane, select by parity
DI uint32_t pick(uint32_t lo, uint32_t hi, int rsel, int src) {
    uint32_t t0 = __shfl_sync(0xffffffffu, lo, src);
    uint32_t t1 = __shfl_sync(0xffffffffu, hi, src);
    return rsel ? t1 : t0;
}

// ---------- pre-kernel: convert basis -> fragment-ordered fp16 global array ----------
extern "C" __global__ void __launch_bounds__(256)
conv_basis(const float* __restrict__ basis)
{
    int s = blockIdx.x * 256 + threadIdx.x;          // 0 .. 13311
    if (s >= B_U2) return;
    int t  = s / STAGE_U2;
    int r  = s - t * STAGE_U2;
    int nt = r >> 5;
    int ln = r & 31;
    int qq = ln & 3;
    int n  = nt * 8 + (ln >> 2);
    uint2 val = make_uint2(0u, 0u);
    if (n < MSZ) {
        int k0 = t * 16 + 2 * qq;
        val.x = cvt_hi(basis[(size_t)k0 * MSZ + n],       basis[(size_t)(k0 + 1) * MSZ + n]);
        val.y = cvt_hi(basis[(size_t)(k0 + 8) * MSZ + n], basis[(size_t)(k0 + 9) * MSZ + n]);
    }
    g_bfrag[s] = val;
}

// ---------- fused kernel: GEMM (fp16 mma.sync, B SMEM-resident, t-pair z loads + shfl)
//            + expm degree-4: E = I + A + A^2*(I/2 + A/6 + A^2/24) ----------
extern "C" __global__ void __launch_bounds__(256, 2)
lie_fused(const float* __restrict__ z, float* __restrict__ out)
{
    extern __shared__ float smem[];
    float* sA = smem;                 // (after GEMM) lie_alg A (never overwritten)
    float* sC = smem + SA_FLOATS;     // (after GEMM) M buffer
    const uint2* sB = (const uint2*)smem;   // (during GEMM) whole B: 13312 uint2
    const uint32_t sb_base = smem_u32(smem);

    const int tid = threadIdx.x, lane = tid & 31, w = tid >> 5;
    const int g = lane >> 2, q = lane & 3;
    const int src  = (lane & 0x1C) | (q >> 1);   // 4g + q/2
    const int src2 = src + 2;
    const int rsel = q & 1;
    const size_t rowBase = (size_t)blockIdx.x * 128;
    const size_t row0 = rowBase + w * 16 + g;
    const float* zr0 = z + row0 * ZDIM;          // row g
    const float* zr1 = zr0 + 8 * ZDIM;           // row g+8

    // ---- load ENTIRE B into SMEM once (6656 x 16B lines, 26 per thread) ----
    {
        const char* gsrc = (const char*)g_bfrag;
#pragma unroll
        for (int i = 0; i < B_LINES / 256; i++) {       // 26
            int idx = i * 256 + tid;
            cpasync16(sb_base + idx * 16, gsrc + idx * 16);
        }
        cpcommit();
    }

    // ---- prefetch z t-pair 0 and convert ----
    uint32_t u[4], v[4];
    {
        float4 F0 = *(const float4*)(zr0 + 4 * q);
        float4 F1 = *(const float4*)(zr0 + 16 + 4 * q);
        float4 G0 = *(const float4*)(zr1 + 4 * q);
        float4 G1 = *(const float4*)(zr1 + 16 + 4 * q);
        u[0] = cvt_hi(F0.x, F0.y); u[1] = cvt_hi(F0.z, F0.w);
        u[2] = cvt_hi(F1.x, F1.y); u[3] = cvt_hi(F1.z, F1.w);
        v[0] = cvt_hi(G0.x, G0.y); v[1] = cvt_hi(G0.z, G0.w);
        v[2] = cvt_hi(G1.x, G1.y); v[3] = cvt_hi(G1.z, G1.w);
    }

    float acc[NT][4];
#pragma unroll
    for (int nt = 0; nt < NT; nt++) { acc[nt][0]=0.f; acc[nt][1]=0.f; acc[nt][2]=0.f; acc[nt][3]=0.f; }

    cpwait0();
    __syncthreads();     // whole B visible; NO barriers inside the main loop

    // ================= GEMM main loop over 16 t-pairs: barrier-free =================
    for (int tp = 0; tp < TSTEPS / 2; tp++) {
        // build BOTH t-steps' A fragments up front (shfl latency hidden by loads below)
        uint32_t Ah0[4], Ah1[4];
        Ah0[0] = pick(u[0], u[1], rsel, src);
        Ah0[1] = pick(v[0], v[1], rsel, src);
        Ah0[2] = pick(u[0], u[1], rsel, src2);
        Ah0[3] = pick(v[0], v[1], rsel, src2);
        Ah1[0] = pick(u[2], u[3], rsel, src);
        Ah1[1] = pick(v[2], v[3], rsel, src);
        Ah1[2] = pick(u[2], u[3], rsel, src2);
        Ah1[3] = pick(v[2], v[3], rsel, src2);

        // issue next pair's z loads (in flight through the MMA work)
        float4 F0, F1, G0, G1;
        const bool more = (tp + 1 < TSTEPS / 2);
        if (more) {
            const float* a0p = zr0 + (tp + 1) * 32 + 4 * q;
            const float* a1p = zr1 + (tp + 1) * 32 + 4 * q;
            F0 = *(const float4*)(a0p);      F1 = *(const float4*)(a0p + 16);
            G0 = *(const float4*)(a1p);      G1 = *(const float4*)(a1p + 16);
        }

        const uint2* bs0 = sB + (size_t)(2 * tp) * STAGE_U2 + lane;
        const uint2* bs1 = bs0 + STAGE_U2;

        // interleaved LDS/HMMA bursts: 7 + 6 per t-step (keeps crossbar and tensor both fed)
        {
            uint2 bb[7];
#pragma unroll
            for (int j = 0; j < 7; j++) bb[j] = bs0[j * 32];
#pragma unroll
            for (int j = 0; j < 7; j++) mma16816(acc[j], Ah0, bb[j].x, bb[j].y);
        }
        {
            uint2 bb[6];
#pragma unroll
            for (int j = 0; j < 6; j++) bb[j] = bs0[(7 + j) * 32];
#pragma unroll
            for (int j = 0; j < 6; j++) mma16816(acc[7 + j], Ah0, bb[j].x, bb[j].y);
        }
        {
            uint2 bb[7];
#pragma unroll
            for (int j = 0; j < 7; j++) bb[j] = bs1[j * 32];
#pragma unroll
            for (int j = 0; j < 7; j++) mma16816(acc[j], Ah1, bb[j].x, bb[j].y);
        }
        {
            uint2 bb[6];
#pragma unroll
            for (int j = 0; j < 6; j++) bb[j] = bs1[(7 + j) * 32];
#pragma unroll
            for (int j = 0; j < 6; j++) mma16816(acc[7 + j], Ah1, bb[j].x, bb[j].y);
        }

        // convert prefetched floats for next pair
        if (more) {
            u[0] = cvt_hi(F0.x, F0.y); u[1] = cvt_hi(F0.z, F0.w);
            u[2] = cvt_hi(F1.x, F1.y); u[3] = cvt_hi(F1.z, F1.w);
            v[0] = cvt_hi(G0.x, G0.y); v[1] = cvt_hi(G0.z, G0.w);
            v[2] = cvt_hi(G1.x, G1.y); v[3] = cvt_hi(G1.z, G1.w);
        }
    }

    __syncthreads();     // all warps done reading B before overwriting region as sA/sC

    // epilogue: fragments -> sA in expm layout
    {
        const int rl0 = w * 16 + g;
#pragma unroll
        for (int nt = 0; nt < NT; nt++) {
            int col = nt * 8 + 2 * q;
            if (col < MSZ) {
                *(float2*)(sA + rl0 * EXP_STR + col)       = make_float2(acc[nt][0], acc[nt][1]);
                *(float2*)(sA + (rl0 + 8) * EXP_STR + col) = make_float2(acc[nt][2], acc[nt][3]);
            }
        }
    }
    __syncthreads();     // lie_alg complete in sA (cross-warp handoff)

    // ================= expm degree-4: E = I + A + A^2 @ M,  M = I/2 + A/6 + A^2/24 ==========
    {
        const int m  = tid >> 1;       // local matrix 0..127
        const int h  = tid & 1;
        const int i0 = 5 * h;
        const int mb = m * EXP_STR;

        ull acc2[5][5];
#pragma unroll
        for (int ii = 0; ii < 5; ii++)
#pragma unroll
            for (int jp = 0; jp < 5; jp++) acc2[ii][jp] = 0ull;

        // A^2 (own rows) -> acc2
#pragma unroll
        for (int kp = 0; kp < 5; kp++) {
            const int k0 = 2 * kp, k1 = k0 + 1;
            ull r0[5], r1[5];
#pragma unroll
            for (int jp = 0; jp < 5; jp++) {
                r0[jp] = lds2(sA + mb + k0 * 10 + 2 * jp);
                r1[jp] = lds2(sA + mb + k1 * 10 + 2 * jp);
            }
#pragma unroll
            for (int ii = 0; ii < 5; ii++) {
                float2 za2 = *(const float2*)(sA + mb + (i0 + ii) * 10 + k0);
                ull z0 = pack2(za2.x), z1 = pack2(za2.y);
#pragma unroll
                for (int jp = 0; jp < 5; jp++) { fma2(acc2[ii][jp], z0, r0[jp]); fma2(acc2[ii][jp], z1, r1[jp]); }
            }
        }

        // M = I/2 + A/6 + A^2/24 -> sC (own rows); sA (=A) stays intact
        {
            const float c1 = 1.f / 6.f, cM = 1.f / 24.f;
#pragma unroll
            for (int ii = 0; ii < 5; ii++) {
                const int gi = i0 + ii;
#pragma unroll
                for (int jp = 0; jp < 5; jp++) {
                    float2 a  = *(const float2*)(sA + mb + gi * 10 + 2 * jp);
                    float2 b2 = unpk(acc2[ii][jp]);
                    float mx = (gi == 2 * jp     ? 0.5f : 0.f) + a.x * c1 + b2.x * cM;
                    float my = (gi == 2 * jp + 1 ? 0.5f : 0.f) + a.y * c1 + b2.y * cM;
                    *(float2*)(sC + mb + gi * 10 + 2 * jp) = make_float2(mx, my);
                }
            }
        }
        __syncwarp();      // M producer/consumer pairs (lanes 2m, 2m+1) are intra-warp

        // E = I + A + A^2 @ M  -> out, two row-groups to bound register pressure
#pragma unroll
        for (int grp = 0; grp < 2; grp++) {
            const int gbase = grp * 3;
            const int rows  = grp == 0 ? 3 : 2;
            ull ae[3][5];
            // init ae = I + A (own rows)
#pragma unroll
            for (int ii = 0; ii < 3; ii++) {
                if (ii < rows) {
                    const int gi = i0 + gbase + ii;
#pragma unroll
                    for (int jp = 0; jp < 5; jp++) {
                        float2 a = *(const float2*)(sA + mb + gi * 10 + 2 * jp);
                        float ex = (gi == 2 * jp     ? 1.f : 0.f) + a.x;
                        float ey = (gi == 2 * jp + 1 ? 1.f : 0.f) + a.y;
                        ae[ii][jp] = pk(ex, ey);
                    }
                }
            }
#pragma unroll
            for (int kp = 0; kp < 5; kp++) {
                const int k0 = 2 * kp, k1 = k0 + 1;
                ull r0[5], r1[5];
#pragma unroll
                for (int jp = 0; jp < 5; jp++) {
                    r0[jp] = lds2(sC + mb + k0 * 10 + 2 * jp);
                    r1[jp] = lds2(sC + mb + k1 * 10 + 2 * jp);
                }
#pragma unroll
                for (int ii = 0; ii < 3; ii++) {
                    if (ii < rows) {
                        float2 f = unpk(acc2[gbase + ii][kp]);
                        ull z0 = pack2(f.x), z1 = pack2(f.y);
#pragma unroll
                        for (int jp = 0; jp < 5; jp++) { fma2(ae[ii][jp], z0, r0[jp]); fma2(ae[ii][jp], z1, r1[jp]); }
                    }
                }
            }
            // store this group's rows (30 or 20 contiguous floats)
            float* op = out + (rowBase + m) * MSZ + (i0 + gbase) * 10;
#pragma unroll
            for (int ii = 0; ii < 3; ii++) {
                if (ii < rows) {
#pragma unroll
                    for (int jp = 0; jp < 5; jp++)
                        *(float2*)(op + ii * 10 + 2 * jp) = unpk(ae[ii][jp]);
                }
            }
        }
    }
}

// ---------------- launch ----------------
extern "C" void kernel_launch(void* const* d_in, const int* in_sizes, int n_in,
                              void* d_out, int out_size)
{
    const float* z     = (const float*)d_in[0];   // [B, 512]
    const float* basis = (const float*)d_in[1];   // [512, 10, 10]
    float* out = (float*)d_out;                   // [B, 10, 10]

    int B = in_sizes[0] / ZDIM;                   // 131072

    cudaFuncSetAttribute(lie_fused, cudaFuncAttributeMaxDynamicSharedMemorySize, SMEM_DYN);

    conv_basis<<<52, 256>>>(basis);               // 13312 fragment slots
    lie_fused<<<B / 128, 256, SMEM_DYN>>>(z, out);
}